// round 3
// baseline (speedup 1.0000x reference)
#include <cuda_runtime.h>

#define SK_N      512
#define SK_ITERS  21
#define SK_THR    512
#define SK_GRID   96           // concurrent CTAs; 96 x 1MB = 96MB < 126MB L2
#define SK_K2     144.26950408889634f   // 100 * log2(e): work in log2 domain
#define SK_GATE   32.0f        // drop terms > 32 log2-units below max (mass < 1.2e-7)

// Dynamic SMEM layout (floats):
//   v[512] | u[512] | stage_m[16*4*32 float4] | stage_p[16*4*32 float4]
#define SK_SMEM_FLOATS (1024 + 2048*4*2)
#define SK_SMEM_BYTES  (SK_SMEM_FLOATS * 4)

// Persistent CTA per matrix (looped). Fused iteration: one read of the matrix
// computes BOTH the row-LSE update u and per-lane online column-LSE partials.
//   u_i     = LSE2_j(s_ij - v_j)                 (s = x * 100 * log2e, log2 domain)
//   v_j_new = v_j_old + LSE2_i(s_ij - v_j_old - u_i)
//           = LSE2_i(s_ij - u_i)                 (exact identity; zp <= 0 always)
//   out     = exp2(s - u - v)
__global__ void __launch_bounds__(SK_THR, 1)
sinkhorn_fused(const float* __restrict__ x, float* __restrict__ out, int nmat)
{
    extern __shared__ float smem[];
    float*  v_s   = smem;                      // 512
    float*  u_s   = smem + 512;                // 512
    float4* stg_m = (float4*)(smem + 1024);    // 2048 float4 (32 KB)
    float4* stg_p = stg_m + 2048;              // 2048 float4 (32 KB)

    const int tid  = threadIdx.x;
    const int lane = tid & 31;
    const int wid  = tid >> 5;                 // 0..15
    const unsigned FULL = 0xffffffffu;

    for (int m = blockIdx.x; m < nmat; m += gridDim.x) {
        const float* __restrict__ X = x   + (size_t)m * SK_N * SK_N;
        float*       __restrict__ O = out + (size_t)m * SK_N * SK_N;

        v_s[tid] = 0.0f;
        __syncthreads();

        for (int it = 0; it < SK_ITERS; ++it) {
            // per-lane online column partials of zp = s - v_old - u (<= 0);
            // lane slot e=4k+jj covers column 128k + 4*lane + jj
            float colm[16], colp[16];
            #pragma unroll
            for (int e = 0; e < 16; ++e) { colm[e] = -3.0e38f; colp[e] = 0.0f; }

            // warp w owns rows [32w, 32w+32)
            for (int rr = 0; rr < 32; ++rr) {
                const int r = wid * 32 + rr;
                const float4* xr = reinterpret_cast<const float4*>(X + (size_t)r * SK_N);
                const float4* vr = reinterpret_cast<const float4*>(v_s);

                float z[16];
                float M = -3.0e38f;
                #pragma unroll
                for (int k = 0; k < 4; ++k) {
                    float4 xv = xr[lane + 32 * k];
                    float4 vv = vr[lane + 32 * k];
                    z[4*k+0] = fmaf(xv.x, SK_K2, -vv.x);
                    z[4*k+1] = fmaf(xv.y, SK_K2, -vv.y);
                    z[4*k+2] = fmaf(xv.z, SK_K2, -vv.z);
                    z[4*k+3] = fmaf(xv.w, SK_K2, -vv.w);
                }
                #pragma unroll
                for (int e = 0; e < 16; ++e) M = fmaxf(M, z[e]);
                #pragma unroll
                for (int o = 16; o > 0; o >>= 1)
                    M = fmaxf(M, __shfl_xor_sync(FULL, M, o));

                // gated row sum (exp only in warp-chunks that have a live term)
                float S = 0.0f;
                const float thr = M - SK_GATE;
                #pragma unroll
                for (int e = 0; e < 16; ++e) {
                    bool c = z[e] > thr;
                    if (__ballot_sync(FULL, c))
                        S += c ? exp2f(z[e] - M) : 0.0f;
                }
                #pragma unroll
                for (int o = 16; o > 0; o >>= 1)
                    S += __shfl_xor_sync(FULL, S, o);

                const float u_r = M + log2f(S);
                if (it == SK_ITERS - 1 && lane == 0) u_s[r] = u_r;

                // fused column partial update: zp = z - u_r <= 0
                #pragma unroll
                for (int e = 0; e < 16; ++e) {
                    float zp = z[e] - u_r;
                    bool  c  = zp > colm[e] - SK_GATE;
                    if (__ballot_sync(FULL, c)) {
                        float mn = fmaxf(colm[e], zp);
                        float sc = exp2f(colm[e] - mn);  // 0 when colm = -3e38
                        float tm = exp2f(zp - mn);
                        if (c) { colp[e] = fmaf(colp[e], sc, tm); colm[e] = mn; }
                    }
                }
            }

            // stage per-warp column partials: [warp][k][lane] float4
            #pragma unroll
            for (int k = 0; k < 4; ++k) {
                stg_m[(wid * 4 + k) * 32 + lane] =
                    make_float4(colm[4*k], colm[4*k+1], colm[4*k+2], colm[4*k+3]);
                stg_p[(wid * 4 + k) * 32 + lane] =
                    make_float4(colp[4*k], colp[4*k+1], colp[4*k+2], colp[4*k+3]);
            }
            __syncthreads();

            // cross-warp combine: thread j owns column j.
            // v_new[j] = v_old[j] + LSE2 over the 16 warp partials.
            {
                const int j  = tid;
                const int kk = j >> 7;
                const int ll = (j >> 2) & 31;
                const int jj = j & 3;

                const float vold = v_s[j];

                float mloc[16];
                float M2 = -3.0e38f;
                #pragma unroll
                for (int w = 0; w < 16; ++w) {
                    mloc[w] = ((const float*)&stg_m[(w * 4 + kk) * 32 + ll])[jj];
                    M2 = fmaxf(M2, mloc[w]);
                }
                float P = 0.0f;
                #pragma unroll
                for (int w = 0; w < 16; ++w) {
                    float pw = ((const float*)&stg_p[(w * 4 + kk) * 32 + ll])[jj];
                    float d  = mloc[w] - M2;
                    P += (d > -SK_GATE) ? pw * exp2f(d) : 0.0f;
                }
                __syncthreads();           // all reads of old v_s done before write
                v_s[j] = vold + M2 + log2f(P);
            }
            __syncthreads();
        }

        // output: exp2(s - u - v)
        for (int rr = 0; rr < 32; ++rr) {
            const int r = wid * 32 + rr;
            const float ur = u_s[r];
            const float4* xr = reinterpret_cast<const float4*>(X + (size_t)r * SK_N);
            const float4* vr = reinterpret_cast<const float4*>(v_s);
            float4* orow = reinterpret_cast<float4*>(O + (size_t)r * SK_N);
            #pragma unroll
            for (int k = 0; k < 4; ++k) {
                float4 xv = xr[lane + 32 * k];
                float4 vv = vr[lane + 32 * k];
                float4 o;
                o.x = exp2f(fmaf(xv.x, SK_K2, -vv.x) - ur);
                o.y = exp2f(fmaf(xv.y, SK_K2, -vv.y) - ur);
                o.z = exp2f(fmaf(xv.z, SK_K2, -vv.z) - ur);
                o.w = exp2f(fmaf(xv.w, SK_K2, -vv.w) - ur);
                orow[lane + 32 * k] = o;
            }
        }
        __syncthreads();   // protect v_s/u_s before next matrix re-init
    }
}

extern "C" void kernel_launch(void* const* d_in, const int* in_sizes, int n_in,
                              void* d_out, int out_size)
{
    const float* x = (const float*)d_in[0];
    float* out = (float*)d_out;
    const int nmat = in_sizes[0] / (SK_N * SK_N);

    cudaFuncSetAttribute(sinkhorn_fused,
                         cudaFuncAttributeMaxDynamicSharedMemorySize, SK_SMEM_BYTES);

    const int grid = nmat < SK_GRID ? nmat : SK_GRID;
    sinkhorn_fused<<<grid, SK_THR, SK_SMEM_BYTES>>>(x, out, nmat);
}

// round 4
// speedup vs baseline: 2.9731x; 2.9731x over previous
#include <cuda_runtime.h>

#define SK_N      512
#define SK_ITERS  21
#define SK_THR    512
#define SK_GRID   128          // 256 matrices = exactly 2 per CTA; ~128MB ~ L2
#define SK_K2     144.26950408889634f   // 100 * log2(e): work in log2 domain
#define SK_CONV   1.52587890625e-05f    // 2^-16 per-iter v-change threshold

__device__ __forceinline__ float ex2f_(float x) {
    float r; asm("ex2.approx.ftz.f32 %0, %1;" : "=f"(r) : "f"(x)); return r;
}
__device__ __forceinline__ float lg2f_(float x) {
    float r; asm("lg2.approx.ftz.f32 %0, %1;" : "=f"(r) : "f"(x)); return r;
}

// Dynamic SMEM (floats): v[512] | u[512] | stg_p[16][512] | stg_m[16][512]
#define SK_SMEM_BYTES ((1024 + 16*512*2) * 4)

// Persistent CTA, 2 matrices each, matrix L2-resident across iterations.
// Fused iteration (ONE matrix read):
//   u_i     = LSE2_j(s_ij - v_j)
//   v_j_new = v_j_old + log2( sum_i exp2(s_ij - v_j_old - u_i) )   [zp <= 0]
//   out     = exp2(s - u - v)
__global__ void __launch_bounds__(SK_THR, 1)
sinkhorn_fused(const float* __restrict__ x, float* __restrict__ out, int nmat)
{
    extern __shared__ float smem[];
    float* v_s   = smem;               // 512
    float* u_s   = smem + 512;         // 512
    float* stg_p = smem + 1024;        // 16*512
    float* stg_m = stg_p + 16 * 512;   // 16*512

    const int tid  = threadIdx.x;
    const int lane = tid & 31;
    const int wid  = tid >> 5;         // 0..15
    const unsigned FULL = 0xffffffffu;

    for (int m = blockIdx.x; m < nmat; m += gridDim.x) {
        const float* __restrict__ X = x   + (size_t)m * SK_N * SK_N;
        float*       __restrict__ O = out + (size_t)m * SK_N * SK_N;

        v_s[tid] = 0.0f;
        __syncthreads();

        for (int it = 0; it < SK_ITERS; ++it) {
            // lane's fixed columns: slot e=4k+jj -> column 128k + 4*lane + jj
            float colv[16];
            {
                const float4* vr = reinterpret_cast<const float4*>(v_s);
                #pragma unroll
                for (int k = 0; k < 4; ++k) {
                    float4 vv = vr[lane + 32 * k];
                    colv[4*k+0] = vv.x; colv[4*k+1] = vv.y;
                    colv[4*k+2] = vv.z; colv[4*k+3] = vv.w;
                }
            }
            float colp[16], colm[16];
            #pragma unroll
            for (int e = 0; e < 16; ++e) { colp[e] = 0.0f; colm[e] = -3.0e38f; }

            // warp w owns rows [32w, 32w+32)
            for (int rr = 0; rr < 32; ++rr) {
                const int r = wid * 32 + rr;
                const float4* xr = reinterpret_cast<const float4*>(X + (size_t)r * SK_N);

                float z[16];
                #pragma unroll
                for (int k = 0; k < 4; ++k) {
                    float4 xv = xr[lane + 32 * k];
                    z[4*k+0] = fmaf(xv.x, SK_K2, -colv[4*k+0]);
                    z[4*k+1] = fmaf(xv.y, SK_K2, -colv[4*k+1]);
                    z[4*k+2] = fmaf(xv.z, SK_K2, -colv[4*k+2]);
                    z[4*k+3] = fmaf(xv.w, SK_K2, -colv[4*k+3]);
                }
                float M = z[0];
                #pragma unroll
                for (int e = 1; e < 16; ++e) M = fmaxf(M, z[e]);
                #pragma unroll
                for (int o = 16; o > 0; o >>= 1)
                    M = fmaxf(M, __shfl_xor_sync(FULL, M, o));

                float S = 0.0f;
                #pragma unroll
                for (int e = 0; e < 16; ++e) S += ex2f_(z[e] - M);
                #pragma unroll
                for (int o = 16; o > 0; o >>= 1)
                    S += __shfl_xor_sync(FULL, S, o);

                const float u_r = M + lg2f_(S);
                if (lane == 0) u_s[r] = u_r;

                // column accumulation vs fixed reference 0 (zp <= 0)
                #pragma unroll
                for (int e = 0; e < 16; ++e) {
                    float zp = z[e] - u_r;
                    colp[e] += ex2f_(zp);
                    colm[e]  = fmaxf(colm[e], zp);
                }
            }

            // stage: stg[w][col], float4 stores, conflict-free
            {
                float4* sp = reinterpret_cast<float4*>(stg_p + wid * 512);
                float4* sm = reinterpret_cast<float4*>(stg_m + wid * 512);
                #pragma unroll
                for (int k = 0; k < 4; ++k) {
                    sp[lane + 32 * k] = make_float4(colp[4*k], colp[4*k+1], colp[4*k+2], colp[4*k+3]);
                    sm[lane + 32 * k] = make_float4(colm[4*k], colm[4*k+1], colm[4*k+2], colm[4*k+3]);
                }
            }
            __syncthreads();

            // combine: thread j owns column j; partials share reference 0
            int active;
            {
                const int j = tid;
                float P  = 0.0f;
                float M2 = -3.0e38f;
                #pragma unroll
                for (int w = 0; w < 16; ++w) {
                    P  += stg_p[w * 512 + j];
                    M2  = fmaxf(M2, stg_m[w * 512 + j]);
                }
                float dv = (P > 0.0f) ? lg2f_(P) : M2;   // fallback: col mass < 2^-126
                v_s[j] += dv;
                active = __syncthreads_count(fabsf(dv) > SK_CONV);
            }
            if (active == 0) break;   // converged: remaining iters are no-ops
        }

        // output: exp2(s - u - v)
        {
            float colv[16];
            const float4* vr = reinterpret_cast<const float4*>(v_s);
            #pragma unroll
            for (int k = 0; k < 4; ++k) {
                float4 vv = vr[lane + 32 * k];
                colv[4*k+0] = vv.x; colv[4*k+1] = vv.y;
                colv[4*k+2] = vv.z; colv[4*k+3] = vv.w;
            }
            for (int rr = 0; rr < 32; ++rr) {
                const int r = wid * 32 + rr;
                const float ur = u_s[r];
                const float4* xr = reinterpret_cast<const float4*>(X + (size_t)r * SK_N);
                float4* orow = reinterpret_cast<float4*>(O + (size_t)r * SK_N);
                #pragma unroll
                for (int k = 0; k < 4; ++k) {
                    float4 xv = xr[lane + 32 * k];
                    float4 o;
                    o.x = ex2f_(fmaf(xv.x, SK_K2, -colv[4*k+0]) - ur);
                    o.y = ex2f_(fmaf(xv.y, SK_K2, -colv[4*k+1]) - ur);
                    o.z = ex2f_(fmaf(xv.z, SK_K2, -colv[4*k+2]) - ur);
                    o.w = ex2f_(fmaf(xv.w, SK_K2, -colv[4*k+3]) - ur);
                    orow[lane + 32 * k] = o;
                }
            }
        }
        __syncthreads();   // protect v_s/u_s before next matrix re-init
    }
}

extern "C" void kernel_launch(void* const* d_in, const int* in_sizes, int n_in,
                              void* d_out, int out_size)
{
    const float* x = (const float*)d_in[0];
    float* out = (float*)d_out;
    const int nmat = in_sizes[0] / (SK_N * SK_N);

    cudaFuncSetAttribute(sinkhorn_fused,
                         cudaFuncAttributeMaxDynamicSharedMemorySize, SK_SMEM_BYTES);

    const int grid = nmat < SK_GRID ? nmat : SK_GRID;
    sinkhorn_fused<<<grid, SK_THR, SK_SMEM_BYTES>>>(x, out, nmat);
}

// round 7
// speedup vs baseline: 3.9549x; 1.3302x over previous
#include <cuda_runtime.h>

#define SK_N      512
#define SK_ITERS  21
#define SK_THR    512
#define SK_GRID   128          // 256 matrices = exactly 2 per CTA
#define SK_K2     144.26950408889634f   // 100 * log2(e): work in log2 domain
#define SK_CONV   1.52587890625e-05f    // 2^-16 per-iter v-change threshold

__device__ __forceinline__ float ex2f_(float x) {
    float r; asm("ex2.approx.ftz.f32 %0, %1;" : "=f"(r) : "f"(x)); return r;
}
__device__ __forceinline__ float lg2f_(float x) {
    float r; asm("lg2.approx.ftz.f32 %0, %1;" : "=f"(r) : "f"(x)); return r;
}
__device__ __forceinline__ float rcpf_(float x) {
    float r; asm("rcp.approx.ftz.f32 %0, %1;" : "=f"(r) : "f"(x)); return r;
}
// evict_last policy register (bias L2 to keep the iteration-read matrix resident)
__device__ __forceinline__ unsigned long long mk_policy_el() {
    unsigned long long p;
    asm("createpolicy.fractional.L2::evict_last.b64 %0, 1.0;" : "=l"(p));
    return p;
}
__device__ __forceinline__ float4 ldg_el(const float4* p, unsigned long long pol) {
    float4 v;
    asm("ld.global.nc.L2::cache_hint.v4.f32 {%0,%1,%2,%3}, [%4], %5;"
        : "=f"(v.x), "=f"(v.y), "=f"(v.z), "=f"(v.w) : "l"(p), "l"(pol));
    return v;
}

// Dynamic SMEM (floats): v[512] | u[512] | stg_p[16][512] | stg_m[16][512]
#define SK_SMEM_BYTES ((1024 + 16*512*2) * 4)

// Persistent CTA, 2 matrices each, matrix biased L2-resident.
// Fused iteration (ONE matrix read):
//   u_i     = LSE2_j(s_ij - v_j)
//   exp2(z - u_i) = exp2(z - M)/S  -> column sums reuse the row exponentials
//   v_j    += log2( sum_i exp2(s_ij - v_j - u_i) )
//   out     = exp2(s - u - v)
__global__ void __launch_bounds__(SK_THR, 1)
sinkhorn_fused(const float* __restrict__ x, float* __restrict__ out, int nmat)
{
    extern __shared__ float smem[];
    float* v_s   = smem;               // 512
    float* u_s   = smem + 512;         // 512
    float* stg_p = smem + 1024;        // 16*512
    float* stg_m = stg_p + 16 * 512;   // 16*512

    const int tid  = threadIdx.x;
    const int lane = tid & 31;
    const int wid  = tid >> 5;         // 0..15
    const unsigned FULL = 0xffffffffu;
    const unsigned long long POL = mk_policy_el();

    for (int m = blockIdx.x; m < nmat; m += gridDim.x) {
        const float* __restrict__ X = x   + (size_t)m * SK_N * SK_N;
        float*       __restrict__ O = out + (size_t)m * SK_N * SK_N;

        v_s[tid] = 0.0f;
        __syncthreads();

        for (int it = 0; it < SK_ITERS; ++it) {
            // lane's fixed columns: slot e=4k+jj -> column 128k + 4*lane + jj
            float colv[16];
            {
                const float4* vr = reinterpret_cast<const float4*>(v_s);
                #pragma unroll
                for (int k = 0; k < 4; ++k) {
                    float4 vv = vr[lane + 32 * k];
                    colv[4*k+0] = vv.x; colv[4*k+1] = vv.y;
                    colv[4*k+2] = vv.z; colv[4*k+3] = vv.w;
                }
            }
            float colp[16], cm[16];
            #pragma unroll
            for (int e = 0; e < 16; ++e) { colp[e] = 0.0f; cm[e] = -3.0e38f; }

            // warp w owns rows [32w, 32w+32); software-pipelined row loads
            float4 pf[4];
            {
                const float4* xr = reinterpret_cast<const float4*>(X + (size_t)(wid * 32) * SK_N);
                #pragma unroll
                for (int k = 0; k < 4; ++k) pf[k] = ldg_el(xr + lane + 32 * k, POL);
            }
            #pragma unroll 1
            for (int rr = 0; rr < 32; ++rr) {
                const int r = wid * 32 + rr;

                float z[16];
                #pragma unroll
                for (int k = 0; k < 4; ++k) {
                    z[4*k+0] = fmaf(pf[k].x, SK_K2, -colv[4*k+0]);
                    z[4*k+1] = fmaf(pf[k].y, SK_K2, -colv[4*k+1]);
                    z[4*k+2] = fmaf(pf[k].z, SK_K2, -colv[4*k+2]);
                    z[4*k+3] = fmaf(pf[k].w, SK_K2, -colv[4*k+3]);
                }
                // prefetch next row while this row computes
                if (rr < 31) {
                    const float4* xn = reinterpret_cast<const float4*>(X + (size_t)(r + 1) * SK_N);
                    #pragma unroll
                    for (int k = 0; k < 4; ++k) pf[k] = ldg_el(xn + lane + 32 * k, POL);
                }

                float M = z[0];
                #pragma unroll
                for (int e = 1; e < 16; ++e) M = fmaxf(M, z[e]);
                #pragma unroll
                for (int o = 16; o > 0; o >>= 1)
                    M = fmaxf(M, __shfl_xor_sync(FULL, M, o));

                // exp in place; track column max (vs M) for dead-column fallback
                float S = 0.0f;
                #pragma unroll
                for (int e = 0; e < 16; ++e) {
                    float d = z[e] - M;
                    cm[e]   = fmaxf(cm[e], d);
                    float t = ex2f_(d);
                    z[e]    = t;
                    S      += t;
                }
                #pragma unroll
                for (int o = 16; o > 0; o >>= 1)
                    S += __shfl_xor_sync(FULL, S, o);

                // S >= 1 analytically (max term contributes 1); clamp so rcp
                // can never produce inf/NaN even in pathological cases
                const float Ssafe = fmaxf(S, 1e-30f);
                const float invS  = rcpf_(Ssafe);
                if (lane == 0) u_s[r] = M + lg2f_(Ssafe);

                // column accumulation: exp2(z - u_r) = t * (1/S)
                #pragma unroll
                for (int e = 0; e < 16; ++e)
                    colp[e] = fmaf(z[e], invS, colp[e]);
            }

            // stage per-warp partials: stg[w][col], float4, conflict-free
            {
                float4* sp = reinterpret_cast<float4*>(stg_p + wid * 512);
                float4* sm = reinterpret_cast<float4*>(stg_m + wid * 512);
                #pragma unroll
                for (int k = 0; k < 4; ++k) {
                    sp[lane + 32 * k] = make_float4(colp[4*k], colp[4*k+1], colp[4*k+2], colp[4*k+3]);
                    sm[lane + 32 * k] = make_float4(cm[4*k],   cm[4*k+1],   cm[4*k+2],   cm[4*k+3]);
                }
            }
            __syncthreads();

            // combine: thread j owns column j; partials share reference 0
            int active;
            {
                const int j = tid;
                float P  = 0.0f;
                float M2 = -3.0e38f;
                #pragma unroll
                for (int w = 0; w < 16; ++w) {
                    P  += stg_p[w * 512 + j];
                    M2  = fmaxf(M2, stg_m[w * 512 + j]);
                }
                // fallback for fully-underflowed columns (mass < 2^-117; and
                // v_new is analytically independent of v_old, so any fallback
                // error self-corrects on the next iteration)
                float dv = (P > 0.0f) ? lg2f_(P) : M2;
                v_s[j] += dv;
                active = __syncthreads_count(fabsf(dv) > SK_CONV);
            }
            if (active == 0) break;   // converged: remaining iters are no-ops
        }

        // output: exp2(s - u - v); streaming read (last use) + streaming store
        {
            float colv[16];
            const float4* vr = reinterpret_cast<const float4*>(v_s);
            #pragma unroll
            for (int k = 0; k < 4; ++k) {
                float4 vv = vr[lane + 32 * k];
                colv[4*k+0] = vv.x; colv[4*k+1] = vv.y;
                colv[4*k+2] = vv.z; colv[4*k+3] = vv.w;
            }
            #pragma unroll 1
            for (int rr = 0; rr < 32; ++rr) {
                const int r = wid * 32 + rr;
                const float ur = u_s[r];
                const float4* xr = reinterpret_cast<const float4*>(X + (size_t)r * SK_N);
                float4* orow = reinterpret_cast<float4*>(O + (size_t)r * SK_N);
                #pragma unroll
                for (int k = 0; k < 4; ++k) {
                    float4 xv = __ldcs(xr + lane + 32 * k);
                    float4 o;
                    o.x = ex2f_(fmaf(xv.x, SK_K2, -colv[4*k+0]) - ur);
                    o.y = ex2f_(fmaf(xv.y, SK_K2, -colv[4*k+1]) - ur);
                    o.z = ex2f_(fmaf(xv.z, SK_K2, -colv[4*k+2]) - ur);
                    o.w = ex2f_(fmaf(xv.w, SK_K2, -colv[4*k+3]) - ur);
                    __stcs(orow + lane + 32 * k, o);
                }
            }
        }
        __syncthreads();   // protect v_s/u_s before next matrix re-init
    }
}

extern "C" void kernel_launch(void* const* d_in, const int* in_sizes, int n_in,
                              void* d_out, int out_size)
{
    const float* x = (const float*)d_in[0];
    float* out = (float*)d_out;
    const int nmat = in_sizes[0] / (SK_N * SK_N);

    cudaFuncSetAttribute(sinkhorn_fused,
                         cudaFuncAttributeMaxDynamicSharedMemorySize, SK_SMEM_BYTES);

    const int grid = nmat < SK_GRID ? nmat : SK_GRID;
    sinkhorn_fused<<<grid, SK_THR, SK_SMEM_BYTES>>>(x, out, nmat);
}

// round 8
// speedup vs baseline: 4.4723x; 1.1308x over previous
#include <cuda_runtime.h>

#define SK_N      512
#define SK_ITERS  21
#define SK_THR    512
#define SK_GRID   128          // 256 matrices = exactly 2 per CTA
#define SK_K2     144.26950408889634f   // 100 * log2(e): work in log2 domain
#define SK_CONV   1.52587890625e-05f    // 2^-16 per-iter v-change threshold

__device__ __forceinline__ float ex2f_(float x) {
    float r; asm("ex2.approx.ftz.f32 %0, %1;" : "=f"(r) : "f"(x)); return r;
}
__device__ __forceinline__ float lg2f_(float x) {
    float r; asm("lg2.approx.ftz.f32 %0, %1;" : "=f"(r) : "f"(x)); return r;
}
__device__ __forceinline__ float rcpf_(float x) {
    float r; asm("rcp.approx.ftz.f32 %0, %1;" : "=f"(r) : "f"(x)); return r;
}
// Fractional policy: 75% of lines evict_last (hot set = 0.75*128MB = 96MB < L2),
// remaining 25% evict_first (streamed). Keeps the protected set under capacity.
__device__ __forceinline__ unsigned long long mk_policy_el() {
    unsigned long long p;
    asm("createpolicy.fractional.L2::evict_last.L2::evict_first.b64 %0, 0.75;"
        : "=l"(p));
    return p;
}
__device__ __forceinline__ float4 ldg_el(const float4* p, unsigned long long pol) {
    float4 v;
    asm("ld.global.nc.L2::cache_hint.v4.f32 {%0,%1,%2,%3}, [%4], %5;"
        : "=f"(v.x), "=f"(v.y), "=f"(v.z), "=f"(v.w) : "l"(p), "l"(pol));
    return v;
}

// Dynamic SMEM (floats): v[512] | u[512] | stg_p[16][512] | stg_m[16][512]
#define SK_SMEM_BYTES ((1024 + 16*512*2) * 4)

// Persistent CTA, 2 matrices each; 75% of each matrix pinned L2-resident.
// Fused iteration (ONE matrix read):
//   u_i     = LSE2_j(s_ij - v_j)
//   exp2(z - u_i) = exp2(z - M)/S  -> column sums reuse the row exponentials
//   v_j    += log2( sum_i exp2(s_ij - v_j - u_i) )
//   out     = exp2(s - u - v)
__global__ void __launch_bounds__(SK_THR, 1)
sinkhorn_fused(const float* __restrict__ x, float* __restrict__ out, int nmat)
{
    extern __shared__ float smem[];
    float* v_s   = smem;               // 512
    float* u_s   = smem + 512;         // 512
    float* stg_p = smem + 1024;        // 16*512
    float* stg_m = stg_p + 16 * 512;   // 16*512

    const int tid  = threadIdx.x;
    const int lane = tid & 31;
    const int wid  = tid >> 5;         // 0..15
    const unsigned FULL = 0xffffffffu;
    const unsigned long long POL = mk_policy_el();

    for (int m = blockIdx.x; m < nmat; m += gridDim.x) {
        const float* __restrict__ X = x   + (size_t)m * SK_N * SK_N;
        float*       __restrict__ O = out + (size_t)m * SK_N * SK_N;

        v_s[tid] = 0.0f;
        __syncthreads();

        for (int it = 0; it < SK_ITERS; ++it) {
            // lane's fixed columns: slot e=4k+jj -> column 128k + 4*lane + jj
            float colv[16];
            {
                const float4* vr = reinterpret_cast<const float4*>(v_s);
                #pragma unroll
                for (int k = 0; k < 4; ++k) {
                    float4 vv = vr[lane + 32 * k];
                    colv[4*k+0] = vv.x; colv[4*k+1] = vv.y;
                    colv[4*k+2] = vv.z; colv[4*k+3] = vv.w;
                }
            }
            float colp[16], cm[16];
            #pragma unroll
            for (int e = 0; e < 16; ++e) { colp[e] = 0.0f; cm[e] = -3.0e38f; }

            // warp w owns rows [32w, 32w+32); software-pipelined row loads
            float4 pf[4];
            {
                const float4* xr = reinterpret_cast<const float4*>(X + (size_t)(wid * 32) * SK_N);
                #pragma unroll
                for (int k = 0; k < 4; ++k) pf[k] = ldg_el(xr + lane + 32 * k, POL);
            }
            #pragma unroll 1
            for (int rr = 0; rr < 32; ++rr) {
                const int r = wid * 32 + rr;

                float z[16];
                #pragma unroll
                for (int k = 0; k < 4; ++k) {
                    z[4*k+0] = fmaf(pf[k].x, SK_K2, -colv[4*k+0]);
                    z[4*k+1] = fmaf(pf[k].y, SK_K2, -colv[4*k+1]);
                    z[4*k+2] = fmaf(pf[k].z, SK_K2, -colv[4*k+2]);
                    z[4*k+3] = fmaf(pf[k].w, SK_K2, -colv[4*k+3]);
                }
                // prefetch next row while this row computes
                if (rr < 31) {
                    const float4* xn = reinterpret_cast<const float4*>(X + (size_t)(r + 1) * SK_N);
                    #pragma unroll
                    for (int k = 0; k < 4; ++k) pf[k] = ldg_el(xn + lane + 32 * k, POL);
                }

                float M = z[0];
                #pragma unroll
                for (int e = 1; e < 16; ++e) M = fmaxf(M, z[e]);
                #pragma unroll
                for (int o = 16; o > 0; o >>= 1)
                    M = fmaxf(M, __shfl_xor_sync(FULL, M, o));

                // exp in place; track column max (vs M) for dead-column fallback
                float S = 0.0f;
                #pragma unroll
                for (int e = 0; e < 16; ++e) {
                    float d = z[e] - M;
                    cm[e]   = fmaxf(cm[e], d);
                    float t = ex2f_(d);
                    z[e]    = t;
                    S      += t;
                }
                #pragma unroll
                for (int o = 16; o > 0; o >>= 1)
                    S += __shfl_xor_sync(FULL, S, o);

                // S >= 1 analytically (max term contributes 1); clamp so rcp
                // can never produce inf/NaN even in pathological cases
                const float Ssafe = fmaxf(S, 1e-30f);
                const float invS  = rcpf_(Ssafe);
                if (lane == 0) u_s[r] = M + lg2f_(Ssafe);

                // column accumulation: exp2(z - u_r) = t * (1/S)
                #pragma unroll
                for (int e = 0; e < 16; ++e)
                    colp[e] = fmaf(z[e], invS, colp[e]);
            }

            // stage per-warp partials: stg[w][col], float4, conflict-free
            {
                float4* sp = reinterpret_cast<float4*>(stg_p + wid * 512);
                float4* sm = reinterpret_cast<float4*>(stg_m + wid * 512);
                #pragma unroll
                for (int k = 0; k < 4; ++k) {
                    sp[lane + 32 * k] = make_float4(colp[4*k], colp[4*k+1], colp[4*k+2], colp[4*k+3]);
                    sm[lane + 32 * k] = make_float4(cm[4*k],   cm[4*k+1],   cm[4*k+2],   cm[4*k+3]);
                }
            }
            __syncthreads();

            // combine: thread j owns column j; partials share reference 0
            int active;
            {
                const int j = tid;
                float P  = 0.0f;
                float M2 = -3.0e38f;
                #pragma unroll
                for (int w = 0; w < 16; ++w) {
                    P  += stg_p[w * 512 + j];
                    M2  = fmaxf(M2, stg_m[w * 512 + j]);
                }
                // fallback for fully-underflowed columns (mass < 2^-117; and
                // v_new is analytically independent of v_old, so any fallback
                // error self-corrects on the next iteration)
                float dv = (P > 0.0f) ? lg2f_(P) : M2;
                v_s[j] += dv;
                active = __syncthreads_count(fabsf(dv) > SK_CONV);
            }
            if (active == 0) break;   // converged: remaining iters are no-ops
        }

        // output: exp2(s - u - v); streaming read (last use) + streaming store
        {
            float colv[16];
            const float4* vr = reinterpret_cast<const float4*>(v_s);
            #pragma unroll
            for (int k = 0; k < 4; ++k) {
                float4 vv = vr[lane + 32 * k];
                colv[4*k+0] = vv.x; colv[4*k+1] = vv.y;
                colv[4*k+2] = vv.z; colv[4*k+3] = vv.w;
            }
            #pragma unroll 1
            for (int rr = 0; rr < 32; ++rr) {
                const int r = wid * 32 + rr;
                const float ur = u_s[r];
                const float4* xr = reinterpret_cast<const float4*>(X + (size_t)r * SK_N);
                float4* orow = reinterpret_cast<float4*>(O + (size_t)r * SK_N);
                #pragma unroll
                for (int k = 0; k < 4; ++k) {
                    float4 xv = __ldcs(xr + lane + 32 * k);
                    float4 o;
                    o.x = ex2f_(fmaf(xv.x, SK_K2, -colv[4*k+0]) - ur);
                    o.y = ex2f_(fmaf(xv.y, SK_K2, -colv[4*k+1]) - ur);
                    o.z = ex2f_(fmaf(xv.z, SK_K2, -colv[4*k+2]) - ur);
                    o.w = ex2f_(fmaf(xv.w, SK_K2, -colv[4*k+3]) - ur);
                    __stcs(orow + lane + 32 * k, o);
                }
            }
        }
        __syncthreads();   // protect v_s/u_s before next matrix re-init
    }
}

extern "C" void kernel_launch(void* const* d_in, const int* in_sizes, int n_in,
                              void* d_out, int out_size)
{
    const float* x = (const float*)d_in[0];
    float* out = (float*)d_out;
    const int nmat = in_sizes[0] / (SK_N * SK_N);

    cudaFuncSetAttribute(sinkhorn_fused,
                         cudaFuncAttributeMaxDynamicSharedMemorySize, SK_SMEM_BYTES);

    const int grid = nmat < SK_GRID ? nmat : SK_GRID;
    sinkhorn_fused<<<grid, SK_THR, SK_SMEM_BYTES>>>(x, out, nmat);
}

// round 9
// speedup vs baseline: 4.8895x; 1.0933x over previous
#include <cuda_runtime.h>

#define SK_N      512
#define SK_ITERS  21
#define SK_THR    512
#define SK_NCLUST 64           // 64 clusters x 2 CTAs = 128 CTAs; 64MB hot set << L2
#define SK_ROWS_PER_CTA 256
#define SK_ROWS_PER_WARP 16
#define SK_K2     144.26950408889634f   // 100 * log2(e): work in log2 domain
#define SK_CONV   1.52587890625e-05f    // 2^-16 per-iter v-change threshold

__device__ __forceinline__ float ex2f_(float x) {
    float r; asm("ex2.approx.ftz.f32 %0, %1;" : "=f"(r) : "f"(x)); return r;
}
__device__ __forceinline__ float lg2f_(float x) {
    float r; asm("lg2.approx.ftz.f32 %0, %1;" : "=f"(r) : "f"(x)); return r;
}
__device__ __forceinline__ float rcpf_(float x) {
    float r; asm("rcp.approx.ftz.f32 %0, %1;" : "=f"(r) : "f"(x)); return r;
}
// full evict_last: protected set is 64MB, comfortably inside L2
__device__ __forceinline__ unsigned long long mk_policy_el() {
    unsigned long long p;
    asm("createpolicy.fractional.L2::evict_last.b64 %0, 1.0;" : "=l"(p));
    return p;
}
__device__ __forceinline__ float4 ldg_el(const float4* p, unsigned long long pol) {
    float4 v;
    asm("ld.global.nc.L2::cache_hint.v4.f32 {%0,%1,%2,%3}, [%4], %5;"
        : "=f"(v.x), "=f"(v.y), "=f"(v.z), "=f"(v.w) : "l"(p), "l"(pol));
    return v;
}
__device__ __forceinline__ unsigned cluster_rank_() {
    unsigned r; asm("mov.u32 %0, %%cluster_ctarank;" : "=r"(r)); return r;
}
// store a float into the PEER CTA's shared memory at the same offset
__device__ __forceinline__ void st_peer_f32(unsigned addr, unsigned peer, float v) {
    asm volatile(
        "{ .reg .b32 r; mapa.shared::cluster.u32 r, %0, %1;"
        "  st.shared::cluster.f32 [r], %2; }"
        :: "r"(addr), "r"(peer), "f"(v) : "memory");
}
__device__ __forceinline__ void cluster_sync_() {
    asm volatile("barrier.cluster.arrive.aligned;" ::: "memory");
    asm volatile("barrier.cluster.wait.aligned;"   ::: "memory");
}

// SMEM floats: v[512] | u[512] | stg_p[16*512] | stg_m[16*512] | pex[2*512] | mex[2*512]
#define OFF_V    0
#define OFF_U    512
#define OFF_SP   1024
#define OFF_SM   (1024 + 8192)
#define OFF_PEX  (1024 + 16384)
#define OFF_MEX  (1024 + 16384 + 1024)
#define SK_SMEM_FLOATS (1024 + 16384 + 2048)
#define SK_SMEM_BYTES  (SK_SMEM_FLOATS * 4)

// Cluster of 2 CTAs per matrix (rank r owns rows [256r, 256r+256)).
// 64 concurrent matrices -> fully L2-resident across all 21 re-reads.
// Per iteration: local row-pass + column partials, push partials to peer via
// DSMEM (parity double-buffered), one cluster barrier, combine:
//   v_j += log2(P_local_j + P_peer_j)
__global__ void __launch_bounds__(SK_THR, 1) __cluster_dims__(2, 1, 1)
sinkhorn_fused(const float* __restrict__ x, float* __restrict__ out, int nmat)
{
    extern __shared__ float smem[];
    float* v_s   = smem + OFF_V;
    float* u_s   = smem + OFF_U;
    float* stg_p = smem + OFF_SP;
    float* stg_m = smem + OFF_SM;
    float* pex   = smem + OFF_PEX;
    float* mex   = smem + OFF_MEX;
    const unsigned smem_b = (unsigned)__cvta_generic_to_shared(smem);

    const int tid  = threadIdx.x;
    const int lane = tid & 31;
    const int wid  = tid >> 5;                 // 0..15
    const unsigned FULL = 0xffffffffu;
    const unsigned rank = cluster_rank_();
    const unsigned peer = rank ^ 1u;
    const int row0 = (int)rank * SK_ROWS_PER_CTA;
    const unsigned long long POL = mk_policy_el();

    const int cid      = blockIdx.x >> 1;
    const int nclust   = gridDim.x >> 1;

    for (int m = cid; m < nmat; m += nclust) {
        const float* __restrict__ X = x   + (size_t)m * SK_N * SK_N;
        float*       __restrict__ O = out + (size_t)m * SK_N * SK_N;

        v_s[tid] = 0.0f;
        __syncthreads();

        for (int it = 0; it < SK_ITERS; ++it) {
            const int par = it & 1;

            // lane's fixed columns: slot e=4k+jj -> column 128k + 4*lane + jj
            float colv[16];
            {
                const float4* vr = reinterpret_cast<const float4*>(v_s);
                #pragma unroll
                for (int k = 0; k < 4; ++k) {
                    float4 vv = vr[lane + 32 * k];
                    colv[4*k+0] = vv.x; colv[4*k+1] = vv.y;
                    colv[4*k+2] = vv.z; colv[4*k+3] = vv.w;
                }
            }
            float colp[16], cm[16];
            #pragma unroll
            for (int e = 0; e < 16; ++e) { colp[e] = 0.0f; cm[e] = -3.0e38f; }

            // warp w owns rows row0 + [16w, 16w+16); software-pipelined loads
            float4 pf[4];
            {
                const float4* xr = reinterpret_cast<const float4*>(
                    X + (size_t)(row0 + wid * SK_ROWS_PER_WARP) * SK_N);
                #pragma unroll
                for (int k = 0; k < 4; ++k) pf[k] = ldg_el(xr + lane + 32 * k, POL);
            }
            #pragma unroll 1
            for (int rr = 0; rr < SK_ROWS_PER_WARP; ++rr) {
                const int r = row0 + wid * SK_ROWS_PER_WARP + rr;

                float z[16];
                #pragma unroll
                for (int k = 0; k < 4; ++k) {
                    z[4*k+0] = fmaf(pf[k].x, SK_K2, -colv[4*k+0]);
                    z[4*k+1] = fmaf(pf[k].y, SK_K2, -colv[4*k+1]);
                    z[4*k+2] = fmaf(pf[k].z, SK_K2, -colv[4*k+2]);
                    z[4*k+3] = fmaf(pf[k].w, SK_K2, -colv[4*k+3]);
                }
                if (rr < SK_ROWS_PER_WARP - 1) {
                    const float4* xn = reinterpret_cast<const float4*>(X + (size_t)(r + 1) * SK_N);
                    #pragma unroll
                    for (int k = 0; k < 4; ++k) pf[k] = ldg_el(xn + lane + 32 * k, POL);
                }

                float M = z[0];
                #pragma unroll
                for (int e = 1; e < 16; ++e) M = fmaxf(M, z[e]);
                #pragma unroll
                for (int o = 16; o > 0; o >>= 1)
                    M = fmaxf(M, __shfl_xor_sync(FULL, M, o));

                float S = 0.0f;
                #pragma unroll
                for (int e = 0; e < 16; ++e) {
                    float d = z[e] - M;
                    cm[e]   = fmaxf(cm[e], d);
                    float t = ex2f_(d);
                    z[e]    = t;
                    S      += t;
                }
                #pragma unroll
                for (int o = 16; o > 0; o >>= 1)
                    S += __shfl_xor_sync(FULL, S, o);

                const float Ssafe = fmaxf(S, 1e-30f);
                const float invS  = rcpf_(Ssafe);
                if (lane == 0) u_s[r] = M + lg2f_(Ssafe);

                #pragma unroll
                for (int e = 0; e < 16; ++e)
                    colp[e] = fmaf(z[e], invS, colp[e]);
            }

            // stage per-warp partials
            {
                float4* sp = reinterpret_cast<float4*>(stg_p + wid * 512);
                float4* sm = reinterpret_cast<float4*>(stg_m + wid * 512);
                #pragma unroll
                for (int k = 0; k < 4; ++k) {
                    sp[lane + 32 * k] = make_float4(colp[4*k], colp[4*k+1], colp[4*k+2], colp[4*k+3]);
                    sm[lane + 32 * k] = make_float4(cm[4*k],   cm[4*k+1],   cm[4*k+2],   cm[4*k+3]);
                }
            }
            __syncthreads();

            // local combine -> push to peer's exchange buffer (parity par)
            const int j = tid;
            float Pl = 0.0f, Ml = -3.0e38f;
            #pragma unroll
            for (int w = 0; w < 16; ++w) {
                Pl += stg_p[w * 512 + j];
                Ml  = fmaxf(Ml, stg_m[w * 512 + j]);
            }
            st_peer_f32(smem_b + (OFF_PEX + par * 512 + j) * 4, peer, Pl);
            st_peer_f32(smem_b + (OFF_MEX + par * 512 + j) * 4, peer, Ml);

            cluster_sync_();   // arrive=release: our DSMEM stores visible to peer

            const float P  = Pl + pex[par * 512 + j];
            const float M2 = fmaxf(Ml, mex[par * 512 + j]);
            // fallback for fully-underflowed columns (self-corrects next iter)
            const float dv = (P > 0.0f) ? lg2f_(P) : M2;
            v_s[j] += dv;
            const int active = __syncthreads_count(fabsf(dv) > SK_CONV);
            if (active == 0) break;   // identical in both CTAs -> coherent exit
        }

        // output: exp2(s - u - v); streaming read (last use) + streaming store
        {
            float colv[16];
            const float4* vr = reinterpret_cast<const float4*>(v_s);
            #pragma unroll
            for (int k = 0; k < 4; ++k) {
                float4 vv = vr[lane + 32 * k];
                colv[4*k+0] = vv.x; colv[4*k+1] = vv.y;
                colv[4*k+2] = vv.z; colv[4*k+3] = vv.w;
            }
            #pragma unroll 1
            for (int rr = 0; rr < SK_ROWS_PER_WARP; ++rr) {
                const int r = row0 + wid * SK_ROWS_PER_WARP + rr;
                const float ur = u_s[r];
                const float4* xr = reinterpret_cast<const float4*>(X + (size_t)r * SK_N);
                float4* orow = reinterpret_cast<float4*>(O + (size_t)r * SK_N);
                #pragma unroll
                for (int k = 0; k < 4; ++k) {
                    float4 xv = __ldcs(xr + lane + 32 * k);
                    float4 o;
                    o.x = ex2f_(fmaf(xv.x, SK_K2, -colv[4*k+0]) - ur);
                    o.y = ex2f_(fmaf(xv.y, SK_K2, -colv[4*k+1]) - ur);
                    o.z = ex2f_(fmaf(xv.z, SK_K2, -colv[4*k+2]) - ur);
                    o.w = ex2f_(fmaf(xv.w, SK_K2, -colv[4*k+3]) - ur);
                    __stcs(orow + lane + 32 * k, o);
                }
            }
        }
        // protect exchange buffers + v_s before the next matrix starts
        cluster_sync_();
        __syncthreads();
    }
}

extern "C" void kernel_launch(void* const* d_in, const int* in_sizes, int n_in,
                              void* d_out, int out_size)
{
    const float* x = (const float*)d_in[0];
    float* out = (float*)d_out;
    const int nmat = in_sizes[0] / (SK_N * SK_N);

    cudaFuncSetAttribute(sinkhorn_fused,
                         cudaFuncAttributeMaxDynamicSharedMemorySize, SK_SMEM_BYTES);

    int nclust = nmat < SK_NCLUST ? nmat : SK_NCLUST;
    sinkhorn_fused<<<2 * nclust, SK_THR, SK_SMEM_BYTES>>>(x, out, nmat);
}

// round 10
// speedup vs baseline: 4.9514x; 1.0127x over previous
#include <cuda_runtime.h>

#define SK_N      512
#define SK_ITERS  21
#define SK_THR    512
#define SK_NCLUST 64           // 64 clusters x 2 CTAs = 128 CTAs; 64MB hot set << L2
#define SK_ROWS_PER_CTA 256
#define SK_ROWS_PER_WARP 16
#define SK_K2     144.26950408889634f   // 100 * log2(e): work in log2 domain
#define SK_CONV   1.52587890625e-05f    // 2^-16 per-iter v-change threshold
#define SK_FLOOR  1.2446e-35f           // 2^-116 colp init: dead-column floor
#define SK_FIX    4194304.0f            // 2^22 fixed-point scale for row sums
#define SK_FIXINV 2.38418579101562e-07f // 2^-22

__device__ __forceinline__ float ex2f_(float x) {
    float r; asm("ex2.approx.ftz.f32 %0, %1;" : "=f"(r) : "f"(x)); return r;
}
__device__ __forceinline__ float lg2f_(float x) {
    float r; asm("lg2.approx.ftz.f32 %0, %1;" : "=f"(r) : "f"(x)); return r;
}
__device__ __forceinline__ float rcpf_(float x) {
    float r; asm("rcp.approx.ftz.f32 %0, %1;" : "=f"(r) : "f"(x)); return r;
}
// monotonic float<->uint order transform (exact warp max via __reduce_max_sync)
__device__ __forceinline__ unsigned f2ord(float f) {
    unsigned b = __float_as_uint(f);
    return b ^ (unsigned)(((int)b >> 31) | 0x80000000);
}
__device__ __forceinline__ float ord2f(unsigned k) {
    return __uint_as_float(k ^ (unsigned)((~(int)k >> 31) | 0x80000000));
}
// full evict_last: protected set is 64MB, comfortably inside L2
__device__ __forceinline__ unsigned long long mk_policy_el() {
    unsigned long long p;
    asm("createpolicy.fractional.L2::evict_last.b64 %0, 1.0;" : "=l"(p));
    return p;
}
__device__ __forceinline__ float4 ldg_el(const float4* p, unsigned long long pol) {
    float4 v;
    asm("ld.global.nc.L2::cache_hint.v4.f32 {%0,%1,%2,%3}, [%4], %5;"
        : "=f"(v.x), "=f"(v.y), "=f"(v.z), "=f"(v.w) : "l"(p), "l"(pol));
    return v;
}
__device__ __forceinline__ unsigned cluster_rank_() {
    unsigned r; asm("mov.u32 %0, %%cluster_ctarank;" : "=r"(r)); return r;
}
__device__ __forceinline__ void st_peer_f32(unsigned addr, unsigned peer, float v) {
    asm volatile(
        "{ .reg .b32 r; mapa.shared::cluster.u32 r, %0, %1;"
        "  st.shared::cluster.f32 [r], %2; }"
        :: "r"(addr), "r"(peer), "f"(v) : "memory");
}
__device__ __forceinline__ void cluster_sync_() {
    asm volatile("barrier.cluster.arrive.aligned;" ::: "memory");
    asm volatile("barrier.cluster.wait.aligned;"   ::: "memory");
}

// SMEM floats: v[512] | M_s[512] | S_s[512] | stg_p[16*512] | pex[2*512]
#define OFF_V    0
#define OFF_M    512
#define OFF_S    1024
#define OFF_SP   1536
#define OFF_PEX  (1536 + 8192)
#define SK_SMEM_FLOATS (1536 + 8192 + 1024)
#define SK_SMEM_BYTES  (SK_SMEM_FLOATS * 4)

// Cluster of 2 CTAs per matrix; 64 concurrent matrices L2-resident.
// Per iteration (ONE matrix read):
//   row pass: M_i = max_j z,  S_i = sum_j exp2(z - M)  (z = s - v)
//   column partials: colp_j += exp2(z - M)/S            (floor-initialized)
//   v_j += log2(P_local + P_peer)                       (DSMEM exchange)
// u_i = M_i + log2(S_i) materialized only in the output pass.
__global__ void __launch_bounds__(SK_THR, 1) __cluster_dims__(2, 1, 1)
sinkhorn_fused(const float* __restrict__ x, float* __restrict__ out, int nmat)
{
    extern __shared__ float smem[];
    float* v_s   = smem + OFF_V;
    float* M_s   = smem + OFF_M;
    float* S_s   = smem + OFF_S;
    float* stg_p = smem + OFF_SP;
    float* pex   = smem + OFF_PEX;
    const unsigned smem_b = (unsigned)__cvta_generic_to_shared(smem);

    const int tid  = threadIdx.x;
    const int lane = tid & 31;
    const int wid  = tid >> 5;                 // 0..15
    const unsigned FULL = 0xffffffffu;
    const unsigned rank = cluster_rank_();
    const unsigned peer = rank ^ 1u;
    const int row0 = (int)rank * SK_ROWS_PER_CTA;
    const unsigned long long POL = mk_policy_el();

    const int cid    = blockIdx.x >> 1;
    const int nclust = gridDim.x >> 1;

    for (int m = cid; m < nmat; m += nclust) {
        const float* __restrict__ X = x   + (size_t)m * SK_N * SK_N;
        float*       __restrict__ O = out + (size_t)m * SK_N * SK_N;

        v_s[tid] = 0.0f;
        __syncthreads();

        for (int it = 0; it < SK_ITERS; ++it) {
            const int par = it & 1;

            // lane's fixed columns: slot e=4k+jj -> column 128k + 4*lane + jj
            float colv[16];
            {
                const float4* vr = reinterpret_cast<const float4*>(v_s);
                #pragma unroll
                for (int k = 0; k < 4; ++k) {
                    float4 vv = vr[lane + 32 * k];
                    colv[4*k+0] = vv.x; colv[4*k+1] = vv.y;
                    colv[4*k+2] = vv.z; colv[4*k+3] = vv.w;
                }
            }
            // floor init: a fully-underflowed column still yields P > 0
            // (dv ~ -111/step, self-correcting; v_new is independent of v_old)
            float colp[16];
            #pragma unroll
            for (int e = 0; e < 16; ++e) colp[e] = SK_FLOOR;

            const int rbase = row0 + wid * SK_ROWS_PER_WARP;

            // one row: z, exact max (ordered-uint redux), fixed-point sum
            // (u32 redux), column accumulation; prefetch for rnext interleaved
            auto row_body = [&](float4 (&pf)[4], int r, int rnext) {
                float z[16];
                #pragma unroll
                for (int k = 0; k < 4; ++k) {
                    z[4*k+0] = fmaf(pf[k].x, SK_K2, -colv[4*k+0]);
                    z[4*k+1] = fmaf(pf[k].y, SK_K2, -colv[4*k+1]);
                    z[4*k+2] = fmaf(pf[k].z, SK_K2, -colv[4*k+2]);
                    z[4*k+3] = fmaf(pf[k].w, SK_K2, -colv[4*k+3]);
                }
                if (rnext >= 0) {
                    const float4* xn = reinterpret_cast<const float4*>(X + (size_t)rnext * SK_N);
                    #pragma unroll
                    for (int k = 0; k < 4; ++k) pf[k] = ldg_el(xn + lane + 32 * k, POL);
                }

                float ml = z[0];
                #pragma unroll
                for (int e = 1; e < 16; ++e) ml = fmaxf(ml, z[e]);
                const float M = ord2f(__reduce_max_sync(FULL, f2ord(ml)));

                float ssum = 0.0f;
                #pragma unroll
                for (int e = 0; e < 16; ++e) {
                    float t = ex2f_(z[e] - M);
                    z[e] = t;
                    ssum += t;
                }
                // S in [1, 512] (M is the exact max); 2^22 fixed point, <=2^31
                const unsigned us = __reduce_add_sync(FULL, __float2uint_rn(ssum * SK_FIX));
                const float S = (float)us * SK_FIXINV;
                const float invS = rcpf_(S);
                if (lane == 0) { M_s[r] = M; S_s[r] = S; }

                #pragma unroll
                for (int e = 0; e < 16; ++e)
                    colp[e] = fmaf(z[e], invS, colp[e]);
            };

            // depth-2 software pipeline over the 16 rows
            float4 pfA[4], pfB[4];
            {
                const float4* x0 = reinterpret_cast<const float4*>(X + (size_t)rbase * SK_N);
                const float4* x1 = reinterpret_cast<const float4*>(X + (size_t)(rbase + 1) * SK_N);
                #pragma unroll
                for (int k = 0; k < 4; ++k) {
                    pfA[k] = ldg_el(x0 + lane + 32 * k, POL);
                    pfB[k] = ldg_el(x1 + lane + 32 * k, POL);
                }
            }
            #pragma unroll 1
            for (int rr = 0; rr < SK_ROWS_PER_WARP; rr += 2) {
                row_body(pfA, rbase + rr,     rr + 2 < SK_ROWS_PER_WARP ? rbase + rr + 2 : -1);
                row_body(pfB, rbase + rr + 1, rr + 3 < SK_ROWS_PER_WARP ? rbase + rr + 3 : -1);
            }

            // stage per-warp column partials
            {
                float4* sp = reinterpret_cast<float4*>(stg_p + wid * 512);
                #pragma unroll
                for (int k = 0; k < 4; ++k)
                    sp[lane + 32 * k] = make_float4(colp[4*k], colp[4*k+1], colp[4*k+2], colp[4*k+3]);
            }
            __syncthreads();

            // local combine -> push to peer (parity double-buffered)
            const int j = tid;
            float Pl = 0.0f;
            #pragma unroll
            for (int w = 0; w < 16; ++w) Pl += stg_p[w * 512 + j];
            st_peer_f32(smem_b + (OFF_PEX + par * 512 + j) * 4, peer, Pl);

            cluster_sync_();   // release our DSMEM store / acquire peer's

            const float P  = Pl + pex[par * 512 + j];   // > 0 by floor
            const float dv = lg2f_(P);
            v_s[j] += dv;
            const int active = __syncthreads_count(fabsf(dv) > SK_CONV);
            if (active == 0) break;   // identical in both CTAs -> coherent exit
        }

        // output: exp2(s - u - v), u = M + log2(S); streaming read + store
        {
            float colv[16];
            const float4* vr = reinterpret_cast<const float4*>(v_s);
            #pragma unroll
            for (int k = 0; k < 4; ++k) {
                float4 vv = vr[lane + 32 * k];
                colv[4*k+0] = vv.x; colv[4*k+1] = vv.y;
                colv[4*k+2] = vv.z; colv[4*k+3] = vv.w;
            }
            #pragma unroll 1
            for (int rr = 0; rr < SK_ROWS_PER_WARP; ++rr) {
                const int r = row0 + wid * SK_ROWS_PER_WARP + rr;
                const float ur = M_s[r] + lg2f_(S_s[r]);
                const float4* xr = reinterpret_cast<const float4*>(X + (size_t)r * SK_N);
                float4* orow = reinterpret_cast<float4*>(O + (size_t)r * SK_N);
                #pragma unroll
                for (int k = 0; k < 4; ++k) {
                    float4 xv = __ldcs(xr + lane + 32 * k);
                    float4 o;
                    o.x = ex2f_(fmaf(xv.x, SK_K2, -colv[4*k+0]) - ur);
                    o.y = ex2f_(fmaf(xv.y, SK_K2, -colv[4*k+1]) - ur);
                    o.z = ex2f_(fmaf(xv.z, SK_K2, -colv[4*k+2]) - ur);
                    o.w = ex2f_(fmaf(xv.w, SK_K2, -colv[4*k+3]) - ur);
                    __stcs(orow + lane + 32 * k, o);
                }
            }
        }
        // protect exchange buffers + v_s before the next matrix starts
        cluster_sync_();
        __syncthreads();
    }
}

extern "C" void kernel_launch(void* const* d_in, const int* in_sizes, int n_in,
                              void* d_out, int out_size)
{
    const float* x = (const float*)d_in[0];
    float* out = (float*)d_out;
    const int nmat = in_sizes[0] / (SK_N * SK_N);

    cudaFuncSetAttribute(sinkhorn_fused,
                         cudaFuncAttributeMaxDynamicSharedMemorySize, SK_SMEM_BYTES);

    int nclust = nmat < SK_NCLUST ? nmat : SK_NCLUST;
    sinkhorn_fused<<<2 * nclust, SK_THR, SK_SMEM_BYTES>>>(x, out, nmat);
}

// round 11
// speedup vs baseline: 5.0556x; 1.0210x over previous
#include <cuda_runtime.h>

#define SK_N      512
#define SK_ITERS  21
#define SK_THR    1024         // 32 warps -> occ 50% (regs capped at 64/thread)
#define SK_NCLUST 64           // 64 clusters x 2 CTAs = 128 CTAs; 64MB hot set << L2
#define SK_ROWS_PER_CTA 256
#define SK_RPW    8            // rows per warp (32 warps x 8 = 256)
#define SK_K2     144.26950408889634f   // 100 * log2(e): work in log2 domain
#define SK_CONV   1.52587890625e-05f    // 2^-16 per-iter v-change threshold
#define SK_FLOOR  1.2446e-35f           // 2^-116 colp init: dead-column floor

__device__ __forceinline__ float ex2f_(float x) {
    float r; asm("ex2.approx.ftz.f32 %0, %1;" : "=f"(r) : "f"(x)); return r;
}
__device__ __forceinline__ float lg2f_(float x) {
    float r; asm("lg2.approx.ftz.f32 %0, %1;" : "=f"(r) : "f"(x)); return r;
}
__device__ __forceinline__ float rcpf_(float x) {
    float r; asm("rcp.approx.ftz.f32 %0, %1;" : "=f"(r) : "f"(x)); return r;
}
// volatile shared load (asm) so ptxas cannot hoist v into registers
#define LDS128F(v, addr)                                                  \
    asm volatile("ld.shared.v4.f32 {%0,%1,%2,%3}, [%4];"                  \
        : "=f"((v).x), "=f"((v).y), "=f"((v).z), "=f"((v).w) : "r"(addr))

__device__ __forceinline__ unsigned cluster_rank_() {
    unsigned r; asm("mov.u32 %0, %%cluster_ctarank;" : "=r"(r)); return r;
}
__device__ __forceinline__ void st_peer_f32(unsigned addr, unsigned peer, float v) {
    asm volatile(
        "{ .reg .b32 r; mapa.shared::cluster.u32 r, %0, %1;"
        "  st.shared::cluster.f32 [r], %2; }"
        :: "r"(addr), "r"(peer), "f"(v) : "memory");
}
__device__ __forceinline__ void cluster_sync_() {
    asm volatile("barrier.cluster.arrive.aligned;" ::: "memory");
    asm volatile("barrier.cluster.wait.aligned;"   ::: "memory");
}

// SMEM floats: v[512] | M_s[512] | S_s[512] | stg_p[32*512] | pex[2*512]
#define OFF_V    0
#define OFF_M    512
#define OFF_S    1024
#define OFF_SP   1536
#define OFF_PEX  (1536 + 32*512)
#define SK_SMEM_FLOATS (1536 + 32*512 + 1024)
#define SK_SMEM_BYTES  (SK_SMEM_FLOATS * 4)

// Cluster of 2 CTAs per matrix (rank r owns rows [256r, 256r+256)).
// 64 concurrent matrices -> L2-resident across all 21 re-reads (no policy
// needed at 64MB). 1024 threads/CTA: 32 warps, 8 rows/warp; latency hidden
// by warp parallelism (8 warps/SMSP) instead of register prefetch.
// Per iteration (ONE matrix read):
//   M_i = max_j z, S_i = sum_j exp2(z-M)   (z = s - v, float shfl reductions)
//   colp_j += exp2(z-M)/S                  (floor-initialized; u deferred)
//   v_j += log2(P_local + P_peer)          (DSMEM exchange, parity-buffered)
__global__ void __launch_bounds__(SK_THR, 1) __cluster_dims__(2, 1, 1)
sinkhorn_fused(const float* __restrict__ x, float* __restrict__ out, int nmat)
{
    extern __shared__ float smem[];
    float* v_s   = smem + OFF_V;
    float* M_s   = smem + OFF_M;
    float* S_s   = smem + OFF_S;
    float* stg_p = smem + OFF_SP;
    float* pex   = smem + OFF_PEX;
    const unsigned smem_b = (unsigned)__cvta_generic_to_shared(smem);
    const unsigned vbase  = smem_b + OFF_V * 4;

    const int tid  = threadIdx.x;
    const int lane = tid & 31;
    const int wid  = tid >> 5;                 // 0..31
    const unsigned FULL = 0xffffffffu;
    const unsigned rank = cluster_rank_();
    const unsigned peer = rank ^ 1u;
    const int row0 = (int)rank * SK_ROWS_PER_CTA;

    const int cid    = blockIdx.x >> 1;
    const int nclust = gridDim.x >> 1;

    for (int m = cid; m < nmat; m += nclust) {
        const float* __restrict__ X = x   + (size_t)m * SK_N * SK_N;
        float*       __restrict__ O = out + (size_t)m * SK_N * SK_N;

        if (tid < SK_N) v_s[tid] = 0.0f;
        __syncthreads();

        for (int it = 0; it < SK_ITERS; ++it) {
            const int par = it & 1;

            // floor init: dead columns still yield P > 0 (self-corrects;
            // v_new is analytically independent of v_old)
            float colp[16];
            #pragma unroll
            for (int e = 0; e < 16; ++e) colp[e] = SK_FLOOR;

            const int rbase = row0 + wid * SK_RPW;

            #pragma unroll 1
            for (int rr = 0; rr < SK_RPW; ++rr) {
                const int r = rbase + rr;
                const float4* xr = reinterpret_cast<const float4*>(X + (size_t)r * SK_N);

                // z = s - v ; v re-read from smem each row (volatile LDS.128,
                // keeps it out of the register file)
                float z[16];
                #pragma unroll
                for (int k = 0; k < 4; ++k) {
                    float4 xv = __ldg(xr + lane + 32 * k);
                    float4 vv; LDS128F(vv, vbase + (unsigned)(lane + 32 * k) * 16);
                    z[4*k+0] = fmaf(xv.x, SK_K2, -vv.x);
                    z[4*k+1] = fmaf(xv.y, SK_K2, -vv.y);
                    z[4*k+2] = fmaf(xv.z, SK_K2, -vv.z);
                    z[4*k+3] = fmaf(xv.w, SK_K2, -vv.w);
                }

                float M = z[0];
                #pragma unroll
                for (int e = 1; e < 16; ++e) M = fmaxf(M, z[e]);
                #pragma unroll
                for (int o = 16; o > 0; o >>= 1)
                    M = fmaxf(M, __shfl_xor_sync(FULL, M, o));

                float S = 0.0f;
                #pragma unroll
                for (int e = 0; e < 16; ++e) {
                    float t = ex2f_(z[e] - M);
                    z[e] = t;
                    S   += t;
                }
                #pragma unroll
                for (int o = 16; o > 0; o >>= 1)
                    S += __shfl_xor_sync(FULL, S, o);

                const float Ssafe = fmaxf(S, 1e-30f);   // S >= 1 analytically
                const float invS  = rcpf_(Ssafe);
                if (lane == 0) { M_s[r] = M; S_s[r] = Ssafe; }

                // column accumulation: exp2(z - u_r) = t * (1/S)
                #pragma unroll
                for (int e = 0; e < 16; ++e)
                    colp[e] = fmaf(z[e], invS, colp[e]);
            }

            // stage per-warp column partials (conflict-free float4)
            {
                float4* sp = reinterpret_cast<float4*>(stg_p + wid * 512);
                #pragma unroll
                for (int k = 0; k < 4; ++k)
                    sp[lane + 32 * k] = make_float4(colp[4*k], colp[4*k+1], colp[4*k+2], colp[4*k+3]);
            }
            __syncthreads();

            // combine: thread j (< 512) owns column j over 32 warp partials
            float dv = 0.0f;
            float Pl = 0.0f;
            if (tid < SK_N) {
                #pragma unroll
                for (int w = 0; w < 32; ++w) Pl += stg_p[w * 512 + tid];
                st_peer_f32(smem_b + (OFF_PEX + par * 512 + tid) * 4, peer, Pl);
            }
            cluster_sync_();   // release our DSMEM store / acquire peer's
            if (tid < SK_N) {
                const float P = Pl + pex[par * 512 + tid];   // > 0 by floor
                dv = lg2f_(P);
                v_s[tid] += dv;
            }
            const int active = __syncthreads_count(fabsf(dv) > SK_CONV);
            if (active == 0) break;   // identical in both CTAs -> coherent exit
        }

        // output: exp2(s - u - v), u = M + log2(S); streaming read + store
        {
            #pragma unroll 1
            for (int rr = 0; rr < SK_RPW; ++rr) {
                const int r = row0 + wid * SK_RPW + rr;
                const float ur = M_s[r] + lg2f_(S_s[r]);
                const float4* xr = reinterpret_cast<const float4*>(X + (size_t)r * SK_N);
                float4* orow = reinterpret_cast<float4*>(O + (size_t)r * SK_N);
                #pragma unroll
                for (int k = 0; k < 4; ++k) {
                    float4 xv = __ldcs(xr + lane + 32 * k);
                    float4 vv; LDS128F(vv, vbase + (unsigned)(lane + 32 * k) * 16);
                    float4 o;
                    o.x = ex2f_(fmaf(xv.x, SK_K2, -vv.x) - ur);
                    o.y = ex2f_(fmaf(xv.y, SK_K2, -vv.y) - ur);
                    o.z = ex2f_(fmaf(xv.z, SK_K2, -vv.z) - ur);
                    o.w = ex2f_(fmaf(xv.w, SK_K2, -vv.w) - ur);
                    __stcs(orow + lane + 32 * k, o);
                }
            }
        }
        // protect exchange buffers + v_s before the next matrix starts
        cluster_sync_();
        __syncthreads();
    }
}

extern "C" void kernel_launch(void* const* d_in, const int* in_sizes, int n_in,
                              void* d_out, int out_size)
{
    const float* x = (const float*)d_in[0];
    float* out = (float*)d_out;
    const int nmat = in_sizes[0] / (SK_N * SK_N);

    cudaFuncSetAttribute(sinkhorn_fused,
                         cudaFuncAttributeMaxDynamicSharedMemorySize, SK_SMEM_BYTES);

    int nclust = nmat < SK_NCLUST ? nmat : SK_NCLUST;
    sinkhorn_fused<<<2 * nclust, SK_THR, SK_SMEM_BYTES>>>(x, out, nmat);
}

// round 12
// speedup vs baseline: 5.2273x; 1.0340x over previous
#include <cuda_runtime.h>

#define SK_N      512
#define SK_ITERS  21
#define SK_THR    1024         // 32 warps -> occ 50% (regs capped at 64/thread)
#define SK_NCLUST 64           // 64 clusters x 2 CTAs = 128 CTAs; 64MB hot set << L2
#define SK_ROWS_PER_CTA 256
#define SK_RPW    8            // rows per warp (32 warps x 8 = 256)
#define SK_K2     144.26950408889634f   // 100 * log2(e): work in log2 domain
#define SK_CONV   1.52587890625e-05f    // 2^-16 per-iter v-change threshold
#define SK_B      112.0f                // exponent bias: term reach z-u > -238
#define SK_2B     5.192296858534828e33f // 2^112
#define SK_FLOOR  1.2446e-35f           // 2^-116 colp init (=> fallback dv ~ -222)

__device__ __forceinline__ float ex2f_(float x) {
    float r; asm("ex2.approx.ftz.f32 %0, %1;" : "=f"(r) : "f"(x)); return r;
}
__device__ __forceinline__ float lg2f_(float x) {
    float r; asm("lg2.approx.ftz.f32 %0, %1;" : "=f"(r) : "f"(x)); return r;
}
__device__ __forceinline__ float rcpf_(float x) {
    float r; asm("rcp.approx.ftz.f32 %0, %1;" : "=f"(r) : "f"(x)); return r;
}
// volatile shared load (asm) so ptxas cannot hoist v into registers
#define LDS128F(v, addr)                                                  \
    asm volatile("ld.shared.v4.f32 {%0,%1,%2,%3}, [%4];"                  \
        : "=f"((v).x), "=f"((v).y), "=f"((v).z), "=f"((v).w) : "r"(addr))

__device__ __forceinline__ unsigned cluster_rank_() {
    unsigned r; asm("mov.u32 %0, %%cluster_ctarank;" : "=r"(r)); return r;
}
__device__ __forceinline__ void st_peer_f32(unsigned addr, unsigned peer, float v) {
    asm volatile(
        "{ .reg .b32 r; mapa.shared::cluster.u32 r, %0, %1;"
        "  st.shared::cluster.f32 [r], %2; }"
        :: "r"(addr), "r"(peer), "f"(v) : "memory");
}
__device__ __forceinline__ void cluster_sync_() {
    asm volatile("barrier.cluster.arrive.aligned;" ::: "memory");
    asm volatile("barrier.cluster.wait.aligned;"   ::: "memory");
}

// SMEM floats: v[512] | M_s[512] | S_s[512] | stg_p[32*512] | pex[2*512]
#define OFF_V    0
#define OFF_M    512
#define OFF_S    1024
#define OFF_SP   1536
#define OFF_PEX  (1536 + 32*512)
#define SK_SMEM_FLOATS (1536 + 32*512 + 1024)
#define SK_SMEM_BYTES  (SK_SMEM_FLOATS * 4)

// Cluster of 2 CTAs per matrix (rank r owns rows [256r, 256r+256)).
// 64 concurrent matrices -> L2-resident across all 21 re-reads.
// Exponent-bias scheme (exact identity, extends FTZ reach to z-u > -238):
//   Mb = M - 112;  t = exp2(z - Mb);  S2 = sum t  (= S_true * 2^112)
//   colp += t * (rcp(S2) * 2^112)    (= exp2(z - u + 112))
//   u = Mb + log2(S2)                 (true u; output pass unchanged)
//   v += log2(P_local + P_peer) - 112
__global__ void __launch_bounds__(SK_THR, 1) __cluster_dims__(2, 1, 1)
sinkhorn_fused(const float* __restrict__ x, float* __restrict__ out, int nmat)
{
    extern __shared__ float smem[];
    float* v_s   = smem + OFF_V;
    float* M_s   = smem + OFF_M;
    float* S_s   = smem + OFF_S;
    float* stg_p = smem + OFF_SP;
    float* pex   = smem + OFF_PEX;
    const unsigned smem_b = (unsigned)__cvta_generic_to_shared(smem);
    const unsigned vbase  = smem_b + OFF_V * 4;

    const int tid  = threadIdx.x;
    const int lane = tid & 31;
    const int wid  = tid >> 5;                 // 0..31
    const unsigned FULL = 0xffffffffu;
    const unsigned rank = cluster_rank_();
    const unsigned peer = rank ^ 1u;
    const int row0 = (int)rank * SK_ROWS_PER_CTA;

    const int cid    = blockIdx.x >> 1;
    const int nclust = gridDim.x >> 1;

    for (int m = cid; m < nmat; m += nclust) {
        const float* __restrict__ X = x   + (size_t)m * SK_N * SK_N;
        float*       __restrict__ O = out + (size_t)m * SK_N * SK_N;

        if (tid < SK_N) v_s[tid] = 0.0f;
        __syncthreads();

        for (int it = 0; it < SK_ITERS; ++it) {
            const int par = it & 1;

            // floor init: dead columns still yield P > 0 (dv ~ -222; self-
            // corrects since v_new is analytically independent of v_old)
            float colp[16];
            #pragma unroll
            for (int e = 0; e < 16; ++e) colp[e] = SK_FLOOR;

            const int rbase = row0 + wid * SK_RPW;

            #pragma unroll 1
            for (int rr = 0; rr < SK_RPW; ++rr) {
                const int r = rbase + rr;
                const float4* xr = reinterpret_cast<const float4*>(X + (size_t)r * SK_N);

                // z = s - v ; v re-read from smem each row (volatile LDS.128)
                float z[16];
                #pragma unroll
                for (int k = 0; k < 4; ++k) {
                    float4 xv = __ldg(xr + lane + 32 * k);
                    float4 vv; LDS128F(vv, vbase + (unsigned)(lane + 32 * k) * 16);
                    z[4*k+0] = fmaf(xv.x, SK_K2, -vv.x);
                    z[4*k+1] = fmaf(xv.y, SK_K2, -vv.y);
                    z[4*k+2] = fmaf(xv.z, SK_K2, -vv.z);
                    z[4*k+3] = fmaf(xv.w, SK_K2, -vv.w);
                }

                float M = z[0];
                #pragma unroll
                for (int e = 1; e < 16; ++e) M = fmaxf(M, z[e]);
                #pragma unroll
                for (int o = 16; o > 0; o >>= 1)
                    M = fmaxf(M, __shfl_xor_sync(FULL, M, o));

                const float Mb = M - SK_B;   // biased reference

                float S2 = 0.0f;
                #pragma unroll
                for (int e = 0; e < 16; ++e) {
                    float t = ex2f_(z[e] - Mb);   // <= 2^112
                    z[e] = t;
                    S2  += t;
                }
                #pragma unroll
                for (int o = 16; o > 0; o >>= 1)
                    S2 += __shfl_xor_sync(FULL, S2, o);

                // S2 in [2^112, 2^121]; rcp stays normal
                const float invSb = rcpf_(S2) * SK_2B;   // = 2^112 / (S*2^112)
                if (lane == 0) { M_s[r] = Mb; S_s[r] = S2; }

                // colp += exp2(z - u + 112): flushes only below z-u = -238
                #pragma unroll
                for (int e = 0; e < 16; ++e)
                    colp[e] = fmaf(z[e], invSb, colp[e]);
            }

            // stage per-warp column partials (conflict-free float4)
            {
                float4* sp = reinterpret_cast<float4*>(stg_p + wid * 512);
                #pragma unroll
                for (int k = 0; k < 4; ++k)
                    sp[lane + 32 * k] = make_float4(colp[4*k], colp[4*k+1], colp[4*k+2], colp[4*k+3]);
            }
            __syncthreads();

            // combine: thread j (< 512) owns column j over 32 warp partials
            float dv = 0.0f;
            float Pl = 0.0f;
            if (tid < SK_N) {
                #pragma unroll
                for (int w = 0; w < 32; ++w) Pl += stg_p[w * 512 + tid];
                st_peer_f32(smem_b + (OFF_PEX + par * 512 + tid) * 4, peer, Pl);
            }
            cluster_sync_();   // release our DSMEM store / acquire peer's
            if (tid < SK_N) {
                const float P = Pl + pex[par * 512 + tid];   // > 0 by floor
                dv = lg2f_(P) - SK_B;
                v_s[tid] += dv;
            }
            const int active = __syncthreads_count(fabsf(dv) > SK_CONV);
            if (active == 0) break;   // identical in both CTAs -> coherent exit
        }

        // output: exp2(s - u - v), u = Mb + log2(S2); streaming read + store
        {
            #pragma unroll 1
            for (int rr = 0; rr < SK_RPW; ++rr) {
                const int r = row0 + wid * SK_RPW + rr;
                const float ur = M_s[r] + lg2f_(S_s[r]);   // true u (bias cancels)
                const float4* xr = reinterpret_cast<const float4*>(X + (size_t)r * SK_N);
                float4* orow = reinterpret_cast<float4*>(O + (size_t)r * SK_N);
                #pragma unroll
                for (int k = 0; k < 4; ++k) {
                    float4 xv = __ldcs(xr + lane + 32 * k);
                    float4 vv; LDS128F(vv, vbase + (unsigned)(lane + 32 * k) * 16);
                    float4 o;
                    o.x = ex2f_(fmaf(xv.x, SK_K2, -vv.x) - ur);
                    o.y = ex2f_(fmaf(xv.y, SK_K2, -vv.y) - ur);
                    o.z = ex2f_(fmaf(xv.z, SK_K2, -vv.z) - ur);
                    o.w = ex2f_(fmaf(xv.w, SK_K2, -vv.w) - ur);
                    __stcs(orow + lane + 32 * k, o);
                }
            }
        }
        // protect exchange buffers + v_s before the next matrix starts
        cluster_sync_();
        __syncthreads();
    }
}

extern "C" void kernel_launch(void* const* d_in, const int* in_sizes, int n_in,
                              void* d_out, int out_size)
{
    const float* x = (const float*)d_in[0];
    float* out = (float*)d_out;
    const int nmat = in_sizes[0] / (SK_N * SK_N);

    cudaFuncSetAttribute(sinkhorn_fused,
                         cudaFuncAttributeMaxDynamicSharedMemorySize, SK_SMEM_BYTES);

    int nclust = nmat < SK_NCLUST ? nmat : SK_NCLUST;
    sinkhorn_fused<<<2 * nclust, SK_THR, SK_SMEM_BYTES>>>(x, out, nmat);
}

// round 13
// speedup vs baseline: 5.3321x; 1.0201x over previous
#include <cuda_runtime.h>

#define SK_N      512
#define SK_ITERS  21
#define SK_THR    1024         // 32 warps -> occ 50% (regs capped at 64/thread)
#define SK_NCLUST 64           // 64 clusters x 2 CTAs = 128 CTAs; 64MB hot set << L2
#define SK_ROWS_PER_CTA 256
#define SK_RPW    8            // rows per warp (32 warps x 8 = 256)
#define SK_K2     144.26950408889634f   // 100 * log2(e): work in log2 domain
#define SK_CONV   1.52587890625e-05f    // 2^-16 per-iter v-change threshold
#define SK_B      112.0f                // exponent bias: term reach z-u > -238
#define SK_2B     5.192296858534828e33f // 2^112
#define SK_FLOOR  1.2446e-35f           // 2^-116 colp init (=> fallback dv ~ -222)

typedef unsigned long long sk_u64;

__device__ __forceinline__ float ex2f_(float x) {
    float r; asm("ex2.approx.ftz.f32 %0, %1;" : "=f"(r) : "f"(x)); return r;
}
__device__ __forceinline__ float lg2f_(float x) {
    float r; asm("lg2.approx.ftz.f32 %0, %1;" : "=f"(r) : "f"(x)); return r;
}
__device__ __forceinline__ float rcpf_(float x) {
    float r; asm("rcp.approx.ftz.f32 %0, %1;" : "=f"(r) : "f"(x)); return r;
}
// ---- packed f32x2 (Blackwell; ptxas never auto-fuses these) ----
__device__ __forceinline__ sk_u64 pk2_(float lo, float hi) {
    sk_u64 r; asm("mov.b64 %0, {%1, %2};" : "=l"(r) : "f"(lo), "f"(hi)); return r;
}
__device__ __forceinline__ void up2_(sk_u64 p, float& lo, float& hi) {
    asm("mov.b64 {%0, %1}, %2;" : "=f"(lo), "=f"(hi) : "l"(p));
}
__device__ __forceinline__ sk_u64 fma2_(sk_u64 a, sk_u64 b, sk_u64 c) {
    sk_u64 r; asm("fma.rn.f32x2 %0, %1, %2, %3;" : "=l"(r) : "l"(a), "l"(b), "l"(c)); return r;
}
__device__ __forceinline__ sk_u64 add2_(sk_u64 a, sk_u64 b) {
    sk_u64 r; asm("add.rn.f32x2 %0, %1, %2;" : "=l"(r) : "l"(a), "l"(b)); return r;
}
// volatile shared load (asm) so ptxas cannot hoist v into registers
#define LDS128F(v, addr)                                                  \
    asm volatile("ld.shared.v4.f32 {%0,%1,%2,%3}, [%4];"                  \
        : "=f"((v).x), "=f"((v).y), "=f"((v).z), "=f"((v).w) : "r"(addr))

__device__ __forceinline__ unsigned cluster_rank_() {
    unsigned r; asm("mov.u32 %0, %%cluster_ctarank;" : "=r"(r)); return r;
}
__device__ __forceinline__ void st_peer_f32(unsigned addr, unsigned peer, float v) {
    asm volatile(
        "{ .reg .b32 r; mapa.shared::cluster.u32 r, %0, %1;"
        "  st.shared::cluster.f32 [r], %2; }"
        :: "r"(addr), "r"(peer), "f"(v) : "memory");
}
__device__ __forceinline__ void cluster_sync_() {
    asm volatile("barrier.cluster.arrive.aligned;" ::: "memory");
    asm volatile("barrier.cluster.wait.aligned;"   ::: "memory");
}

// SMEM floats: nv[512] (= -v) | M_s[512] | S_s[512] | stg_p[32*512] | pex[2*512]
#define OFF_V    0
#define OFF_M    512
#define OFF_S    1024
#define OFF_SP   1536
#define OFF_PEX  (1536 + 32*512)
#define SK_SMEM_FLOATS (1536 + 32*512 + 1024)
#define SK_SMEM_BYTES  (SK_SMEM_FLOATS * 4)

// Cluster of 2 CTAs per matrix; 64 concurrent matrices L2-resident.
// smem nv = -v so z = fma2(x, K2, nv) needs no negate (packed-friendly).
// Exponent-bias row pass (identical math to R12, packed f32x2 ops):
//   Mb = M-112; t = exp2(z-Mb) (<=2^112); S2 = sum t
//   colp += t * (rcp(S2)*2^112);  u = Mb + log2(S2) (deferred to output)
//   nv_j -= (log2(P_local+P_peer) - 112)
__global__ void __launch_bounds__(SK_THR, 1) __cluster_dims__(2, 1, 1)
sinkhorn_fused(const float* __restrict__ x, float* __restrict__ out, int nmat)
{
    extern __shared__ float smem[];
    float* v_s   = smem + OFF_V;     // holds -v
    float* M_s   = smem + OFF_M;
    float* S_s   = smem + OFF_S;
    float* stg_p = smem + OFF_SP;
    float* pex   = smem + OFF_PEX;
    const unsigned smem_b = (unsigned)__cvta_generic_to_shared(smem);
    const unsigned vbase  = smem_b + OFF_V * 4;

    const int tid  = threadIdx.x;
    const int lane = tid & 31;
    const int wid  = tid >> 5;                 // 0..31
    const unsigned FULL = 0xffffffffu;
    const unsigned rank = cluster_rank_();
    const unsigned peer = rank ^ 1u;
    const int row0 = (int)rank * SK_ROWS_PER_CTA;
    const sk_u64 K2_2 = pk2_(SK_K2, SK_K2);

    const int cid    = blockIdx.x >> 1;
    const int nclust = gridDim.x >> 1;

    for (int m = cid; m < nmat; m += nclust) {
        const float* __restrict__ X = x   + (size_t)m * SK_N * SK_N;
        float*       __restrict__ O = out + (size_t)m * SK_N * SK_N;

        if (tid < SK_N) v_s[tid] = 0.0f;
        __syncthreads();

        for (int it = 0; it < SK_ITERS; ++it) {
            const int par = it & 1;

            // floor init: dead columns still yield P > 0 (self-corrects;
            // v_new is analytically independent of v_old)
            sk_u64 colp2[8];
            const sk_u64 FLOOR2 = pk2_(SK_FLOOR, SK_FLOOR);
            #pragma unroll
            for (int e = 0; e < 8; ++e) colp2[e] = FLOOR2;

            const int rbase = row0 + wid * SK_RPW;

            #pragma unroll 1
            for (int rr = 0; rr < SK_RPW; ++rr) {
                const int r = rbase + rr;
                const float4* xr = reinterpret_cast<const float4*>(X + (size_t)r * SK_N);

                // z = s + nv (packed fma); nv re-read from smem per row
                sk_u64 z2[8];
                #pragma unroll
                for (int k = 0; k < 4; ++k) {
                    float4 xv = __ldg(xr + lane + 32 * k);
                    float4 nv; LDS128F(nv, vbase + (unsigned)(lane + 32 * k) * 16);
                    z2[2*k]   = fma2_(pk2_(xv.x, xv.y), K2_2, pk2_(nv.x, nv.y));
                    z2[2*k+1] = fma2_(pk2_(xv.z, xv.w), K2_2, pk2_(nv.z, nv.w));
                }

                // exact row max (scalar fmnmx over register-pair halves)
                float M = -3.0e38f;
                #pragma unroll
                for (int e = 0; e < 8; ++e) {
                    float a, b; up2_(z2[e], a, b);
                    M = fmaxf(M, fmaxf(a, b));
                }
                #pragma unroll
                for (int o = 16; o > 0; o >>= 1)
                    M = fmaxf(M, __shfl_xor_sync(FULL, M, o));

                // biased exp + packed sum: t = exp2(z - (M-112)) <= 2^112
                const sk_u64 mMb2 = pk2_(SK_B - M, SK_B - M);
                sk_u64 s2acc = pk2_(0.0f, 0.0f);
                #pragma unroll
                for (int e = 0; e < 8; ++e) {
                    sk_u64 w = add2_(z2[e], mMb2);
                    float a, b; up2_(w, a, b);
                    sk_u64 t = pk2_(ex2f_(a), ex2f_(b));
                    z2[e] = t;
                    s2acc = add2_(s2acc, t);
                }
                float sl, sh; up2_(s2acc, sl, sh);
                float S2 = sl + sh;
                #pragma unroll
                for (int o = 16; o > 0; o >>= 1)
                    S2 += __shfl_xor_sync(FULL, S2, o);

                // S2 in [2^112, 2^121]; rcp stays normal
                const float invSb = rcpf_(S2) * SK_2B;
                if (lane == 0) { M_s[r] = M - SK_B; S_s[r] = S2; }

                // colp += exp2(z - u + 112)  (packed fma)
                const sk_u64 inv2 = pk2_(invSb, invSb);
                #pragma unroll
                for (int e = 0; e < 8; ++e)
                    colp2[e] = fma2_(z2[e], inv2, colp2[e]);
            }

            // stage per-warp column partials (conflict-free float4)
            {
                float4* sp = reinterpret_cast<float4*>(stg_p + wid * 512);
                #pragma unroll
                for (int k = 0; k < 4; ++k) {
                    float4 o4;
                    up2_(colp2[2*k],   o4.x, o4.y);
                    up2_(colp2[2*k+1], o4.z, o4.w);
                    sp[lane + 32 * k] = o4;
                }
            }
            __syncthreads();

            // combine: thread j (< 512) owns column j over 32 warp partials
            float dv = 0.0f;
            float Pl = 0.0f;
            if (tid < SK_N) {
                #pragma unroll
                for (int w = 0; w < 32; ++w) Pl += stg_p[w * 512 + tid];
                st_peer_f32(smem_b + (OFF_PEX + par * 512 + tid) * 4, peer, Pl);
            }
            cluster_sync_();   // release our DSMEM store / acquire peer's
            if (tid < SK_N) {
                const float P = Pl + pex[par * 512 + tid];   // > 0 by floor
                dv = lg2f_(P) - SK_B;
                v_s[tid] -= dv;          // nv convention: nv -= dv
            }
            const int active = __syncthreads_count(fabsf(dv) > SK_CONV);
            if (active == 0) break;   // identical in both CTAs -> coherent exit
        }

        // output: exp2(s + nv - u), u = Mb + log2(S2); packed, streaming
        {
            #pragma unroll 1
            for (int rr = 0; rr < SK_RPW; ++rr) {
                const int r = row0 + wid * SK_RPW + rr;
                const float ur = M_s[r] + lg2f_(S_s[r]);   // true u (bias cancels)
                const sk_u64 mu2 = pk2_(-ur, -ur);
                const float4* xr = reinterpret_cast<const float4*>(X + (size_t)r * SK_N);
                float4* orow = reinterpret_cast<float4*>(O + (size_t)r * SK_N);
                #pragma unroll
                for (int k = 0; k < 4; ++k) {
                    float4 xv = __ldcs(xr + lane + 32 * k);
                    float4 nv; LDS128F(nv, vbase + (unsigned)(lane + 32 * k) * 16);
                    sk_u64 a2 = add2_(fma2_(pk2_(xv.x, xv.y), K2_2, pk2_(nv.x, nv.y)), mu2);
                    sk_u64 b2 = add2_(fma2_(pk2_(xv.z, xv.w), K2_2, pk2_(nv.z, nv.w)), mu2);
                    float4 o;
                    { float a, b; up2_(a2, a, b); o.x = ex2f_(a); o.y = ex2f_(b); }
                    { float a, b; up2_(b2, a, b); o.z = ex2f_(a); o.w = ex2f_(b); }
                    __stcs(orow + lane + 32 * k, o);
                }
            }
        }
        // protect exchange buffers + v_s before the next matrix starts
        cluster_sync_();
        __syncthreads();
    }
}

extern "C" void kernel_launch(void* const* d_in, const int* in_sizes, int n_in,
                              void* d_out, int out_size)
{
    const float* x = (const float*)d_in[0];
    float* out = (float*)d_out;
    const int nmat = in_sizes[0] / (SK_N * SK_N);

    cudaFuncSetAttribute(sinkhorn_fused,
                         cudaFuncAttributeMaxDynamicSharedMemorySize, SK_SMEM_BYTES);

    int nclust = nmat < SK_NCLUST ? nmat : SK_NCLUST;
    sinkhorn_fused<<<2 * nclust, SK_THR, SK_SMEM_BYTES>>>(x, out, nmat);
}

// round 14
// speedup vs baseline: 6.0968x; 1.1434x over previous
#include <cuda_runtime.h>

#define SK_N      512
#define SK_ITERS  21
#define SK_THR    768          // 24 warps, occ 37.5%, reg cap 85 (nv fits in regs)
#define SK_NCLUST 64           // 64 clusters x 2 CTAs = 128 CTAs; 64MB hot set << L2
#define SK_ROWS_PER_CTA 256
#define SK_K2     144.26950408889634f   // 100 * log2(e): work in log2 domain
#define SK_CONV   1.52587890625e-05f    // 2^-16 per-iter v-change threshold
#define SK_B      112.0f                // exponent bias: term reach z-u > -238
#define SK_2B     5.192296858534828e33f // 2^112
#define SK_FLOOR  1.2446e-35f           // 2^-116 colp init (=> fallback dv ~ -222)

typedef unsigned long long sk_u64;

__device__ __forceinline__ float ex2f_(float x) {
    float r; asm("ex2.approx.ftz.f32 %0, %1;" : "=f"(r) : "f"(x)); return r;
}
__device__ __forceinline__ float lg2f_(float x) {
    float r; asm("lg2.approx.ftz.f32 %0, %1;" : "=f"(r) : "f"(x)); return r;
}
__device__ __forceinline__ float rcpf_(float x) {
    float r; asm("rcp.approx.ftz.f32 %0, %1;" : "=f"(r) : "f"(x)); return r;
}
// monotonic float<->uint order transform (EXACT warp max via __reduce_max_sync;
// note: unlike R10, the SUM stays a float shfl tree — only max uses redux)
__device__ __forceinline__ unsigned f2ord(float f) {
    unsigned b = __float_as_uint(f);
    return b ^ (unsigned)(((int)b >> 31) | 0x80000000);
}
__device__ __forceinline__ float ord2f(unsigned k) {
    return __uint_as_float(k ^ (unsigned)((~(int)k >> 31) | 0x80000000));
}
// ---- packed f32x2 (Blackwell; ptxas never auto-fuses these) ----
__device__ __forceinline__ sk_u64 pk2_(float lo, float hi) {
    sk_u64 r; asm("mov.b64 %0, {%1, %2};" : "=l"(r) : "f"(lo), "f"(hi)); return r;
}
__device__ __forceinline__ void up2_(sk_u64 p, float& lo, float& hi) {
    asm("mov.b64 {%0, %1}, %2;" : "=f"(lo), "=f"(hi) : "l"(p));
}
__device__ __forceinline__ sk_u64 fma2_(sk_u64 a, sk_u64 b, sk_u64 c) {
    sk_u64 r; asm("fma.rn.f32x2 %0, %1, %2, %3;" : "=l"(r) : "l"(a), "l"(b), "l"(c)); return r;
}
__device__ __forceinline__ sk_u64 add2_(sk_u64 a, sk_u64 b) {
    sk_u64 r; asm("add.rn.f32x2 %0, %1, %2;" : "=l"(r) : "l"(a), "l"(b)); return r;
}
__device__ __forceinline__ unsigned cluster_rank_() {
    unsigned r; asm("mov.u32 %0, %%cluster_ctarank;" : "=r"(r)); return r;
}
__device__ __forceinline__ void st_peer_f32(unsigned addr, unsigned peer, float v) {
    asm volatile(
        "{ .reg .b32 r; mapa.shared::cluster.u32 r, %0, %1;"
        "  st.shared::cluster.f32 [r], %2; }"
        :: "r"(addr), "r"(peer), "f"(v) : "memory");
}
__device__ __forceinline__ void cluster_sync_() {
    asm volatile("barrier.cluster.arrive.aligned;" ::: "memory");
    asm volatile("barrier.cluster.wait.aligned;"   ::: "memory");
}

// SMEM floats: nv[512] (= -v) | M_s[512] | S_s[512] | stg_p[24*512] | pex[2*512]
#define OFF_V    0
#define OFF_M    512
#define OFF_S    1024
#define OFF_SP   1536
#define OFF_PEX  (1536 + 24*512)
#define SK_SMEM_FLOATS (1536 + 24*512 + 1024)
#define SK_SMEM_BYTES  (SK_SMEM_FLOATS * 4)

// Cluster of 2 CTAs per matrix; 64 concurrent matrices L2-resident.
// nv (= -v) hoisted to packed registers ONCE per iteration (no in-loop LDS);
// row max via exact redux; row sum via float shfl tree; exponent-bias scheme:
//   Mb = M-112; t = exp2(z-Mb) (<=2^112); S2 = sum t
//   colp += t * (rcp(S2)*2^112);  u = Mb + log2(S2) (deferred to output)
//   nv_j -= (log2(P_local+P_peer) - 112)
__global__ void __launch_bounds__(SK_THR, 1) __cluster_dims__(2, 1, 1)
sinkhorn_fused(const float* __restrict__ x, float* __restrict__ out, int nmat)
{
    extern __shared__ float smem[];
    float* v_s   = smem + OFF_V;     // holds -v
    float* M_s   = smem + OFF_M;
    float* S_s   = smem + OFF_S;
    float* stg_p = smem + OFF_SP;
    float* pex   = smem + OFF_PEX;
    const unsigned smem_b = (unsigned)__cvta_generic_to_shared(smem);

    const int tid  = threadIdx.x;
    const int lane = tid & 31;
    const int wid  = tid >> 5;                 // 0..23
    const unsigned FULL = 0xffffffffu;
    const unsigned rank = cluster_rank_();
    const unsigned peer = rank ^ 1u;
    const int row0 = (int)rank * SK_ROWS_PER_CTA;
    const sk_u64 K2_2 = pk2_(SK_K2, SK_K2);

    // 256 rows over 24 warps: warps 0-15 take 11 rows, warps 16-23 take 10
    const int nrows = (wid < 16) ? 11 : 10;
    const int rwoff = (wid < 16) ? wid * 11 : 176 + (wid - 16) * 10;

    const int cid    = blockIdx.x >> 1;
    const int nclust = gridDim.x >> 1;

    for (int m = cid; m < nmat; m += nclust) {
        const float* __restrict__ X = x   + (size_t)m * SK_N * SK_N;
        float*       __restrict__ O = out + (size_t)m * SK_N * SK_N;

        if (tid < SK_N) v_s[tid] = 0.0f;
        __syncthreads();

        for (int it = 0; it < SK_ITERS; ++it) {
            const int par = it & 1;

            // hoist nv into packed registers ONCE per iteration
            sk_u64 colv2[8];
            {
                const float4* vr = reinterpret_cast<const float4*>(v_s);
                #pragma unroll
                for (int k = 0; k < 4; ++k) {
                    float4 nv = vr[lane + 32 * k];
                    colv2[2*k]   = pk2_(nv.x, nv.y);
                    colv2[2*k+1] = pk2_(nv.z, nv.w);
                }
            }
            // floor init: dead columns still yield P > 0 (self-corrects;
            // v_new is analytically independent of v_old)
            sk_u64 colp2[8];
            const sk_u64 FLOOR2 = pk2_(SK_FLOOR, SK_FLOOR);
            #pragma unroll
            for (int e = 0; e < 8; ++e) colp2[e] = FLOOR2;

            const int rbase = row0 + rwoff;

            #pragma unroll 1
            for (int rr = 0; rr < nrows; ++rr) {
                const int r = rbase + rr;
                const float4* xr = reinterpret_cast<const float4*>(X + (size_t)r * SK_N);

                // z = s + nv (packed fma, nv from registers)
                sk_u64 z2[8];
                #pragma unroll
                for (int k = 0; k < 4; ++k) {
                    float4 xv = __ldg(xr + lane + 32 * k);
                    z2[2*k]   = fma2_(pk2_(xv.x, xv.y), K2_2, colv2[2*k]);
                    z2[2*k+1] = fma2_(pk2_(xv.z, xv.w), K2_2, colv2[2*k+1]);
                }

                // exact row max: local fmnmx chain + single REDUX
                float ml = -3.0e38f;
                #pragma unroll
                for (int e = 0; e < 8; ++e) {
                    float a, b; up2_(z2[e], a, b);
                    ml = fmaxf(ml, fmaxf(a, b));
                }
                const float M = ord2f(__reduce_max_sync(FULL, f2ord(ml)));

                // biased exp + packed sum: t = exp2(z - (M-112)) <= 2^112
                const sk_u64 mMb2 = pk2_(SK_B - M, SK_B - M);
                sk_u64 s2acc = pk2_(0.0f, 0.0f);
                #pragma unroll
                for (int e = 0; e < 8; ++e) {
                    sk_u64 w = add2_(z2[e], mMb2);
                    float a, b; up2_(w, a, b);
                    sk_u64 t = pk2_(ex2f_(a), ex2f_(b));
                    z2[e] = t;
                    s2acc = add2_(s2acc, t);
                }
                float sl, sh; up2_(s2acc, sl, sh);
                float S2 = sl + sh;
                #pragma unroll
                for (int o = 16; o > 0; o >>= 1)
                    S2 += __shfl_xor_sync(FULL, S2, o);

                // S2 in [2^112, 2^121]; rcp stays normal
                const float invSb = rcpf_(S2) * SK_2B;
                if (lane == 0) { M_s[r] = M - SK_B; S_s[r] = S2; }

                // colp += exp2(z - u + 112)  (packed fma)
                const sk_u64 inv2 = pk2_(invSb, invSb);
                #pragma unroll
                for (int e = 0; e < 8; ++e)
                    colp2[e] = fma2_(z2[e], inv2, colp2[e]);
            }

            // stage per-warp column partials (conflict-free float4)
            {
                float4* sp = reinterpret_cast<float4*>(stg_p + wid * 512);
                #pragma unroll
                for (int k = 0; k < 4; ++k) {
                    float4 o4;
                    up2_(colp2[2*k],   o4.x, o4.y);
                    up2_(colp2[2*k+1], o4.z, o4.w);
                    sp[lane + 32 * k] = o4;
                }
            }
            __syncthreads();

            // combine: thread j (< 512) owns column j over 24 warp partials
            float dv = 0.0f;
            float Pl = 0.0f;
            if (tid < SK_N) {
                #pragma unroll
                for (int w = 0; w < 24; ++w) Pl += stg_p[w * 512 + tid];
                st_peer_f32(smem_b + (OFF_PEX + par * 512 + tid) * 4, peer, Pl);
            }
            cluster_sync_();   // release our DSMEM store / acquire peer's
            if (tid < SK_N) {
                const float P = Pl + pex[par * 512 + tid];   // > 0 by floor
                dv = lg2f_(P) - SK_B;
                v_s[tid] -= dv;          // nv convention: nv -= dv
            }
            const int active = __syncthreads_count(fabsf(dv) > SK_CONV);
            if (active == 0) break;   // identical in both CTAs -> coherent exit
        }

        // output: exp2(s + nv - u), u = Mb + log2(S2); packed, streaming
        {
            sk_u64 colv2[8];
            const float4* vr = reinterpret_cast<const float4*>(v_s);
            #pragma unroll
            for (int k = 0; k < 4; ++k) {
                float4 nv = vr[lane + 32 * k];
                colv2[2*k]   = pk2_(nv.x, nv.y);
                colv2[2*k+1] = pk2_(nv.z, nv.w);
            }
            #pragma unroll 1
            for (int rr = 0; rr < nrows; ++rr) {
                const int r = row0 + rwoff + rr;
                const float ur = M_s[r] + lg2f_(S_s[r]);   // true u (bias cancels)
                const sk_u64 mu2 = pk2_(-ur, -ur);
                const float4* xr = reinterpret_cast<const float4*>(X + (size_t)r * SK_N);
                float4* orow = reinterpret_cast<float4*>(O + (size_t)r * SK_N);
                #pragma unroll
                for (int k = 0; k < 4; ++k) {
                    float4 xv = __ldcs(xr + lane + 32 * k);
                    sk_u64 a2 = add2_(fma2_(pk2_(xv.x, xv.y), K2_2, colv2[2*k]),   mu2);
                    sk_u64 b2 = add2_(fma2_(pk2_(xv.z, xv.w), K2_2, colv2[2*k+1]), mu2);
                    float4 o;
                    { float a, b; up2_(a2, a, b); o.x = ex2f_(a); o.y = ex2f_(b); }
                    { float a, b; up2_(b2, a, b); o.z = ex2f_(a); o.w = ex2f_(b); }
                    __stcs(orow + lane + 32 * k, o);
                }
            }
        }
        // protect exchange buffers + v_s before the next matrix starts
        cluster_sync_();
        __syncthreads();
    }
}

extern "C" void kernel_launch(void* const* d_in, const int* in_sizes, int n_in,
                              void* d_out, int out_size)
{
    const float* x = (const float*)d_in[0];
    float* out = (float*)d_out;
    const int nmat = in_sizes[0] / (SK_N * SK_N);

    cudaFuncSetAttribute(sinkhorn_fused,
                         cudaFuncAttributeMaxDynamicSharedMemorySize, SK_SMEM_BYTES);

    int nclust = nmat < SK_NCLUST ? nmat : SK_NCLUST;
    sinkhorn_fused<<<2 * nclust, SK_THR, SK_SMEM_BYTES>>>(x, out, nmat);
}